// round 1
// baseline (speedup 1.0000x reference)
#include <cuda_runtime.h>
#include <cstdint>

// Problem constants
#define Tn   2048
#define Cdim 4096
#define NH   32
#define NKV  8
#define Dh   128
#define HDq  (NH*Dh)    // 4096
#define HDkv (NKV*Dh)   // 1024

// ---------------- scratch (device globals; no allocation) ----------------
__device__ float g_tq[Tn * HDq];    // x @ Wq  (t, h*128+d)
__device__ float g_tk[Tn * HDkv];   // x @ Wk
__device__ float g_tv[Tn * HDkv];   // x @ Wv
__device__ float g_qh[(size_t)NH * Tn * Dh];  // roped q, head-major (h,t,d)
__device__ float g_yb[Tn * Cdim];   // attention output (t, h*128+d)

// ---------------- generic fp32 tiled GEMM: C = A(MxK) @ B(KxN) ----------------
// A row-major lda=K, B row-major ldb=N, C row-major ldc=N.
// Block tile 128x128, k-tile 16, 256 threads, 8x8 microtile.
__global__ void __launch_bounds__(256) sgemm_kernel(
    const float* __restrict__ A, const float* __restrict__ B, float* __restrict__ C,
    int M, int N, int K)
{
    __shared__ float As[16][132];
    __shared__ float Bs[16][132];

    const int tid = threadIdx.x;
    const int tx = tid & 15;
    const int ty = tid >> 4;
    const int row0 = blockIdx.y * 128;
    const int col0 = blockIdx.x * 128;

    float acc[8][8];
#pragma unroll
    for (int i = 0; i < 8; i++)
#pragma unroll
        for (int j = 0; j < 8; j++) acc[i][j] = 0.f;

    const int arow = tid >> 2;         // 0..63
    const int akc  = (tid & 3) * 4;    // 0,4,8,12
    const int bk   = tid >> 5;         // 0..7
    const int bcol = (tid & 31) * 4;   // 0..124

    for (int k0 = 0; k0 < K; k0 += 16) {
        float4 a0 = *(const float4*)&A[(size_t)(row0 + arow) * K + k0 + akc];
        float4 a1 = *(const float4*)&A[(size_t)(row0 + 64 + arow) * K + k0 + akc];
        float4 b0 = *(const float4*)&B[(size_t)(k0 + bk) * N + col0 + bcol];
        float4 b1 = *(const float4*)&B[(size_t)(k0 + 8 + bk) * N + col0 + bcol];
        __syncthreads();
        As[akc + 0][arow] = a0.x;  As[akc + 1][arow] = a0.y;
        As[akc + 2][arow] = a0.z;  As[akc + 3][arow] = a0.w;
        As[akc + 0][64 + arow] = a1.x;  As[akc + 1][64 + arow] = a1.y;
        As[akc + 2][64 + arow] = a1.z;  As[akc + 3][64 + arow] = a1.w;
        *(float4*)&Bs[bk][bcol]     = b0;
        *(float4*)&Bs[bk + 8][bcol] = b1;
        __syncthreads();
#pragma unroll
        for (int kk = 0; kk < 16; kk++) {
            float4 xa0 = *(const float4*)&As[kk][ty * 4];
            float4 xa1 = *(const float4*)&As[kk][64 + ty * 4];
            float4 xb0 = *(const float4*)&Bs[kk][tx * 4];
            float4 xb1 = *(const float4*)&Bs[kk][64 + tx * 4];
            float av[8] = {xa0.x, xa0.y, xa0.z, xa0.w, xa1.x, xa1.y, xa1.z, xa1.w};
            float bv[8] = {xb0.x, xb0.y, xb0.z, xb0.w, xb1.x, xb1.y, xb1.z, xb1.w};
#pragma unroll
            for (int i = 0; i < 8; i++)
#pragma unroll
                for (int j = 0; j < 8; j++) acc[i][j] += av[i] * bv[j];
        }
    }

#pragma unroll
    for (int i = 0; i < 8; i++) {
        int r = row0 + ((i < 4) ? (ty * 4 + i) : (64 + ty * 4 + (i - 4)));
        float4 o0 = make_float4(acc[i][0], acc[i][1], acc[i][2], acc[i][3]);
        float4 o1 = make_float4(acc[i][4], acc[i][5], acc[i][6], acc[i][7]);
        *(float4*)&C[(size_t)r * N + col0 + tx * 4]      = o0;
        *(float4*)&C[(size_t)r * N + col0 + 64 + tx * 4] = o1;
    }
}

// ---------------- RoPE on q: (t, h*128+d) -> head-major (h,t,d) ----------------
__global__ void __launch_bounds__(256) rope_q_kernel(
    const float* __restrict__ cosb, const float* __restrict__ sinb)
{
    int idx = blockIdx.x * 256 + threadIdx.x;        // NH*Tn*64 total
    if (idx >= NH * Tn * 64) return;
    int d = idx & 63;
    int t = (idx >> 6) & (Tn - 1);
    int h = idx >> 17;
    float u1 = g_tq[t * HDq + h * Dh + d];
    float u2 = g_tq[t * HDq + h * Dh + d + 64];
    float c1 = cosb[t * Dh + d],      s1 = sinb[t * Dh + d];
    float c2 = cosb[t * Dh + d + 64], s2 = sinb[t * Dh + d + 64];
    size_t o = ((size_t)h * Tn + t) * Dh + d;
    g_qh[o]      = u1 * c1 - u2 * s1;
    g_qh[o + 64] = u2 * c2 + u1 * s2;
}

// ---------------- RoPE on k + transpose v, writing the secondary outputs ----------------
__global__ void __launch_bounds__(256) rope_kv_kernel(
    const float* __restrict__ cosb, const float* __restrict__ sinb,
    float* __restrict__ outK, float* __restrict__ outV)
{
    int idx = blockIdx.x * 256 + threadIdx.x;        // NKV*Tn*64 total
    if (idx >= NKV * Tn * 64) return;
    int d  = idx & 63;
    int t  = (idx >> 6) & (Tn - 1);
    int kh = idx >> 17;
    float u1 = g_tk[t * HDkv + kh * Dh + d];
    float u2 = g_tk[t * HDkv + kh * Dh + d + 64];
    float c1 = cosb[t * Dh + d],      s1 = sinb[t * Dh + d];
    float c2 = cosb[t * Dh + d + 64], s2 = sinb[t * Dh + d + 64];
    size_t o = ((size_t)kh * Tn + t) * Dh + d;
    outK[o]      = u1 * c1 - u2 * s1;
    outK[o + 64] = u2 * c2 + u1 * s2;
    outV[o]      = g_tv[t * HDkv + kh * Dh + d];
    outV[o + 64] = g_tv[t * HDkv + kh * Dh + d + 64];
}

// ---------------- fp32 flash attention (causal, no scaling) ----------------
// grid (Tn/64, NH), 256 threads. BM=BN=64, D=128.
// Thread layout: r = tid>>2 owns one query row; quad = tid&3 owns 32 output cols.
#define FLASH_SMEM_FLOATS (3 * 64 * 128 + 64 * 65)
__global__ void __launch_bounds__(256) flash_kernel(
    const float* __restrict__ Kp, const float* __restrict__ Vp)
{
    extern __shared__ float sm[];
    float* qs = sm;                    // 64*128
    float* ks = sm + 8192;             // 64*128
    float* vs = sm + 16384;            // 64*128
    float* ps = sm + 24576;            // 64*65 (padded)

    const int tid  = threadIdx.x;
    const int quad = tid & 3;
    const int r    = tid >> 2;         // 0..63
    const int bq   = blockIdx.x;
    const int h    = blockIdx.y;
    const int tq0  = bq * 64;

    const float4* Q4 = (const float4*)(g_qh + ((size_t)h * Tn + tq0) * Dh);
    const float4* K4 = (const float4*)(Kp + (size_t)(h >> 2) * Tn * Dh);
    const float4* V4 = (const float4*)(Vp + (size_t)(h >> 2) * Tn * Dh);

    float4* qs4 = (float4*)qs;
    float4* ks4 = (float4*)ks;
    float4* vs4 = (float4*)vs;

#pragma unroll
    for (int i = 0; i < 8; i++) qs4[tid + 256 * i] = Q4[tid + 256 * i];

    float acc[32];
#pragma unroll
    for (int i = 0; i < 32; i++) acc[i] = 0.f;
    float mrow = -1e30f, lrow = 0.f;

    for (int j = 0; j <= bq; j++) {
        __syncthreads();
        const float4* Ksrc = K4 + (size_t)j * 64 * 32;
        const float4* Vsrc = V4 + (size_t)j * 64 * 32;
#pragma unroll
        for (int i = 0; i < 8; i++) {
            ks4[tid + 256 * i] = Ksrc[tid + 256 * i];
            vs4[tid + 256 * i] = Vsrc[tid + 256 * i];
        }
        __syncthreads();

        // scores for this row, cols quad*16..quad*16+15
        float sc[16];
#pragma unroll
        for (int jj = 0; jj < 16; jj++) sc[jj] = 0.f;
        const float4* qrow = (const float4*)(qs + r * Dh);
#pragma unroll 4
        for (int d4 = 0; d4 < 32; d4++) {
            float4 qv = qrow[d4];
#pragma unroll
            for (int jj = 0; jj < 16; jj++) {
                float4 kv = ks4[(quad * 16 + jj) * 32 + d4];
                sc[jj] += qv.x * kv.x + qv.y * kv.y + qv.z * kv.z + qv.w * kv.w;
            }
        }

        if (j == bq) {
#pragma unroll
            for (int jj = 0; jj < 16; jj++)
                if (quad * 16 + jj > r) sc[jj] = -1e30f;
        }

        float mloc = sc[0];
#pragma unroll
        for (int jj = 1; jj < 16; jj++) mloc = fmaxf(mloc, sc[jj]);
        mloc = fmaxf(mloc, __shfl_xor_sync(0xffffffffu, mloc, 1));
        mloc = fmaxf(mloc, __shfl_xor_sync(0xffffffffu, mloc, 2));
        float mnew  = fmaxf(mrow, mloc);
        float scale = __expf(mrow - mnew);
        float lloc = 0.f;
#pragma unroll
        for (int jj = 0; jj < 16; jj++) {
            float p = __expf(sc[jj] - mnew);
            sc[jj] = p;
            lloc += p;
        }
        lloc += __shfl_xor_sync(0xffffffffu, lloc, 1);
        lloc += __shfl_xor_sync(0xffffffffu, lloc, 2);
        lrow = lrow * scale + lloc;
        mrow = mnew;
#pragma unroll
        for (int i = 0; i < 32; i++) acc[i] *= scale;
#pragma unroll
        for (int jj = 0; jj < 16; jj++) ps[r * 65 + quad * 16 + jj] = sc[jj];
        __syncthreads();

        // PV: acc[c] += sum_s p[s] * v[s][c]
#pragma unroll 4
        for (int s = 0; s < 64; s++) {
            float pp = ps[r * 65 + s];
            const float4* vrow = vs4 + s * 32 + quad * 8;
#pragma unroll
            for (int cc = 0; cc < 8; cc++) {
                float4 vv = vrow[cc];
                acc[cc * 4 + 0] += pp * vv.x;
                acc[cc * 4 + 1] += pp * vv.y;
                acc[cc * 4 + 2] += pp * vv.z;
                acc[cc * 4 + 3] += pp * vv.w;
            }
        }
    }

    float inv = 1.f / lrow;
    float* yrow = g_yb + (size_t)(tq0 + r) * Cdim + h * Dh + quad * 32;
#pragma unroll
    for (int cc = 0; cc < 8; cc++) {
        float4 o = make_float4(acc[cc * 4 + 0] * inv, acc[cc * 4 + 1] * inv,
                               acc[cc * 4 + 2] * inv, acc[cc * 4 + 3] * inv);
        *(float4*)(yrow + cc * 4) = o;
    }
}

// ---------------- launch ----------------
extern "C" void kernel_launch(void* const* d_in, const int* in_sizes, int n_in,
                              void* d_out, int out_size)
{
    const float* x    = (const float*)d_in[0];
    const float* Wq   = (const float*)d_in[1];
    const float* Wk   = (const float*)d_in[2];
    const float* Wv   = (const float*)d_in[3];
    const float* Wo   = (const float*)d_in[4];
    const float* cosb = (const float*)d_in[5];
    const float* sinb = (const float*)d_in[6];
    // d_in[7] = mask, replicated exactly by causal structure (exp underflow), unused

    float* out  = (float*)d_out;
    float* outY = out;                                   // (Tn, Cdim)
    float* outK = out + (size_t)Tn * Cdim;               // (NKV, Tn, Dh)
    float* outV = outK + (size_t)NKV * Tn * Dh;          // (NKV, Tn, Dh)

    float *tq, *tk, *tv, *yb;
    cudaGetSymbolAddress((void**)&tq, g_tq);
    cudaGetSymbolAddress((void**)&tk, g_tk);
    cudaGetSymbolAddress((void**)&tv, g_tv);
    cudaGetSymbolAddress((void**)&yb, g_yb);

    const int flash_smem = FLASH_SMEM_FLOATS * (int)sizeof(float);  // 114,944 B
    cudaFuncSetAttribute(flash_kernel, cudaFuncAttributeMaxDynamicSharedMemorySize,
                         flash_smem);

    // 1-3. QKV projections
    sgemm_kernel<<<dim3(HDq / 128, Tn / 128), 256>>>(x, Wq, tq, Tn, HDq, Cdim);
    sgemm_kernel<<<dim3(HDkv / 128, Tn / 128), 256>>>(x, Wk, tk, Tn, HDkv, Cdim);
    sgemm_kernel<<<dim3(HDkv / 128, Tn / 128), 256>>>(x, Wv, tv, Tn, HDkv, Cdim);

    // 4-5. RoPE + layout transforms (k/v go straight to the output buffer)
    rope_q_kernel<<<(NH * Tn * 64) / 256, 256>>>(cosb, sinb);
    rope_kv_kernel<<<(NKV * Tn * 64) / 256, 256>>>(cosb, sinb, outK, outV);

    // 6. causal flash attention
    flash_kernel<<<dim3(Tn / 64, NH), 256, flash_smem>>>(outK, outV);

    // 7. output projection
    sgemm_kernel<<<dim3(Cdim / 128, Tn / 128), 256>>>(yb, Wo, outY, Tn, Cdim, Cdim);
}

// round 3
// speedup vs baseline: 1.2106x; 1.2106x over previous
#include <cuda_runtime.h>
#include <cuda_bf16.h>
#include <cstdint>

// Problem constants
#define Tn   2048
#define Cdim 4096
#define NH   32
#define NKV  8
#define Dh   128
#define HDq  (NH*Dh)    // 4096
#define HDkv (NKV*Dh)   // 1024

// ---------------- scratch (device globals; no allocation) ----------------
__device__ __align__(256) float g_tq[Tn * HDq];
__device__ __align__(256) float g_tk[Tn * HDkv];
__device__ __align__(256) float g_tv[Tn * HDkv];
__device__ __align__(256) float g_qh[(size_t)NH * Tn * Dh];
__device__ __align__(256) float g_yb[Tn * Cdim];

__device__ __align__(256) __nv_bfloat16 g_xhi[Tn * Cdim];
__device__ __align__(256) __nv_bfloat16 g_xlo[Tn * Cdim];
__device__ __align__(256) __nv_bfloat16 g_ybhi[Tn * Cdim];
__device__ __align__(256) __nv_bfloat16 g_yblo[Tn * Cdim];
__device__ __align__(256) __nv_bfloat16 g_wqhi[(size_t)HDq * Cdim];
__device__ __align__(256) __nv_bfloat16 g_wqlo[(size_t)HDq * Cdim];
__device__ __align__(256) __nv_bfloat16 g_wkhi[(size_t)HDkv * Cdim];
__device__ __align__(256) __nv_bfloat16 g_wklo[(size_t)HDkv * Cdim];
__device__ __align__(256) __nv_bfloat16 g_wvhi[(size_t)HDkv * Cdim];
__device__ __align__(256) __nv_bfloat16 g_wvlo[(size_t)HDkv * Cdim];
__device__ __align__(256) __nv_bfloat16 g_wohi[(size_t)Cdim * Cdim];
__device__ __align__(256) __nv_bfloat16 g_wolo[(size_t)Cdim * Cdim];

// ---------------- baseline-ISA helpers (sm_80+ PTX only) ----------------
__device__ __forceinline__ uint32_t smem_u32(const void* p) {
    uint32_t a;
    asm("{ .reg .u64 t; cvta.to.shared.u64 t, %1; cvt.u32.u64 %0, t; }" : "=r"(a) : "l"(p));
    return a;
}

#define CP_ASYNC16(sm, gp) \
    asm volatile("cp.async.cg.shared.global [%0], [%1], 16;" :: "r"(sm), "l"(gp) : "memory")
#define CP_COMMIT() asm volatile("cp.async.commit_group;" ::: "memory")
#define CP_WAIT(n)  asm volatile("cp.async.wait_group %0;" :: "n"(n) : "memory")

__device__ __forceinline__ void ldsm4(uint32_t* r, uint32_t addr) {
    asm volatile("ldmatrix.sync.aligned.m8n8.x4.shared.b16 {%0,%1,%2,%3}, [%4];"
        : "=r"(r[0]), "=r"(r[1]), "=r"(r[2]), "=r"(r[3]) : "r"(addr));
}

__device__ __forceinline__ void mma_bf16(float* c, const uint32_t* a, const uint32_t* b) {
    asm volatile(
        "mma.sync.aligned.m16n8k16.row.col.f32.bf16.bf16.f32 "
        "{%0,%1,%2,%3}, {%4,%5,%6,%7}, {%8,%9}, {%0,%1,%2,%3};"
        : "+f"(c[0]), "+f"(c[1]), "+f"(c[2]), "+f"(c[3])
        : "r"(a[0]), "r"(a[1]), "r"(a[2]), "r"(a[3]), "r"(b[0]), "r"(b[1]));
}

// ---------------- split x (fp32 -> hi/lo bf16) ----------------
__global__ void __launch_bounds__(256) split_kernel(
    const float* __restrict__ X, __nv_bfloat16* __restrict__ hi,
    __nv_bfloat16* __restrict__ lo)
{
    int idx = blockIdx.x * 256 + threadIdx.x;
    float v = X[idx];
    __nv_bfloat16 h = __float2bfloat16(v);
    hi[idx] = h;
    lo[idx] = __float2bfloat16(v - __bfloat162float(h));
}

// ---------------- transpose+split W [K,N] fp32 -> [N,K] hi/lo bf16 ----------------
__global__ void __launch_bounds__(256) tsplit_kernel(
    const float* __restrict__ W, __nv_bfloat16* __restrict__ Thi,
    __nv_bfloat16* __restrict__ Tlo, int K, int N)
{
    __shared__ float tile[32][33];
    int n0 = blockIdx.x * 32, k0 = blockIdx.y * 32;
    int tx = threadIdx.x & 31, ty = threadIdx.x >> 5;
#pragma unroll
    for (int j = 0; j < 4; j++)
        tile[ty + 8 * j][tx] = W[(size_t)(k0 + ty + 8 * j) * N + n0 + tx];
    __syncthreads();
#pragma unroll
    for (int j = 0; j < 4; j++) {
        int n = ty + 8 * j;
        float v = tile[tx][n];
        __nv_bfloat16 h = __float2bfloat16(v);
        __nv_bfloat16 l = __float2bfloat16(v - __bfloat162float(h));
        size_t o = (size_t)(n0 + n) * K + k0 + tx;
        Thi[o] = h;
        Tlo[o] = l;
    }
}

// ---------------- mma.sync split-bf16 GEMM ----------------
// C[M,N] = A[M,K] * B^T (B stored [N,K], K-contiguous). A,B as hi/lo bf16 pairs.
// 128x128 CTA tile, BK=32, 256 threads (8 warps, 2x4), warp tile 64x32.
// SMEM: row pitch 80B (40 bf16) -> conflict-free ldmatrix.
#define PITCH   80
#define T_A     10240                 // 128 rows * 80B
#define T_STAGE (4 * T_A)             // Ah, Al, Bh, Bl
#define G_SMEM  (2 * T_STAGE)         // 81920 bytes

__device__ __forceinline__ void g_load_pair(
    uint32_t sbase, const __nv_bfloat16* __restrict__ hi,
    const __nv_bfloat16* __restrict__ lo, int rbase, int kc, int K, int tid)
{
#pragma unroll
    for (int i = 0; i < 2; i++) {
        int s = tid + 256 * i;          // 512 segments of 16B per tile
        int row = s >> 2, part = s & 3;
        size_t go = (size_t)(rbase + row) * K + (size_t)kc * 32 + part * 8;
        uint32_t so = (uint32_t)(row * PITCH + part * 16);
        CP_ASYNC16(sbase + so, hi + go);
        CP_ASYNC16(sbase + T_A + so, lo + go);
    }
}

__global__ void __launch_bounds__(256) tcgemm_kernel(
    const __nv_bfloat16* __restrict__ Ahi, const __nv_bfloat16* __restrict__ Alo,
    const __nv_bfloat16* __restrict__ Bhi, const __nv_bfloat16* __restrict__ Blo,
    float* __restrict__ C, int N, int K)
{
    extern __shared__ char smc[];
    const uint32_t sb0 = smem_u32(smc);
    const int tid  = threadIdx.x;
    const int lane = tid & 31;
    const int wid  = tid >> 5;
    const int wm   = wid & 1;           // 0..1  (64-row slab)
    const int wn   = wid >> 1;          // 0..3  (32-col slab)
    const int row0 = blockIdx.y * 128;
    const int col0 = blockIdx.x * 128;

    float acc[4][4][4];
#pragma unroll
    for (int m = 0; m < 4; m++)
#pragma unroll
        for (int n = 0; n < 4; n++)
#pragma unroll
            for (int e = 0; e < 4; e++) acc[m][n][e] = 0.f;

    // ldmatrix per-lane address components
    const uint32_t a_row = (uint32_t)(wm * 64 + (lane & 15));
    const uint32_t a_kb  = (uint32_t)((lane >> 4) * 16);
    const int bmat = lane >> 3, bwin = lane & 7;
    const uint32_t b_n  = (uint32_t)(wn * 32 + bwin + (bmat >> 1) * 8);
    const uint32_t b_kb = (uint32_t)((bmat & 1) * 16);

    const int nk = K >> 5;

    // prologue: chunk 0 -> stage 0
    g_load_pair(sb0,                  Ahi, Alo, row0, 0, K, tid);
    g_load_pair(sb0 + 2 * T_A,        Bhi, Blo, col0, 0, K, tid);
    CP_COMMIT();

    for (int kc = 0; kc < nk; kc++) {
        uint32_t sb = sb0 + (uint32_t)(kc & 1) * T_STAGE;
        if (kc + 1 < nk) {
            uint32_t sb2 = sb0 + (uint32_t)((kc + 1) & 1) * T_STAGE;
            g_load_pair(sb2,           Ahi, Alo, row0, kc + 1, K, tid);
            g_load_pair(sb2 + 2 * T_A, Bhi, Blo, col0, kc + 1, K, tid);
            CP_COMMIT();
            CP_WAIT(1);
        } else {
            CP_WAIT(0);
        }
        __syncthreads();

        const uint32_t aB = sb + a_row * PITCH + a_kb;
        const uint32_t bB = sb + 2 * T_A + b_n * PITCH + b_kb;

#pragma unroll
        for (int ks = 0; ks < 2; ks++) {
            uint32_t ah[4][4], al[4][4], bh[2][4], bl[2][4];
#pragma unroll
            for (int m = 0; m < 4; m++) {
                ldsm4(ah[m], aB + (uint32_t)(m * 16 * PITCH) + ks * 32);
                ldsm4(al[m], aB + T_A + (uint32_t)(m * 16 * PITCH) + ks * 32);
            }
#pragma unroll
            for (int p = 0; p < 2; p++) {
                ldsm4(bh[p], bB + (uint32_t)(p * 16 * PITCH) + ks * 32);
                ldsm4(bl[p], bB + T_A + (uint32_t)(p * 16 * PITCH) + ks * 32);
            }
#pragma unroll
            for (int m = 0; m < 4; m++)
#pragma unroll
                for (int p = 0; p < 2; p++)
#pragma unroll
                    for (int h = 0; h < 2; h++) {
                        float* c = acc[m][p * 2 + h];
                        uint32_t bhh[2] = {bh[p][h * 2], bh[p][h * 2 + 1]};
                        uint32_t bll[2] = {bl[p][h * 2], bl[p][h * 2 + 1]};
                        mma_bf16(c, ah[m], bhh);
                        mma_bf16(c, ah[m], bll);
                        mma_bf16(c, al[m], bhh);
                    }
        }
        __syncthreads();
    }

    // epilogue
    const int g = lane >> 2, t = lane & 3;
#pragma unroll
    for (int m = 0; m < 4; m++) {
        int r0 = row0 + wm * 64 + m * 16 + g;
#pragma unroll
        for (int n = 0; n < 4; n++) {
            int c = col0 + wn * 32 + n * 8 + 2 * t;
            *(float2*)&C[(size_t)r0 * N + c] = make_float2(acc[m][n][0], acc[m][n][1]);
            *(float2*)&C[(size_t)(r0 + 8) * N + c] = make_float2(acc[m][n][2], acc[m][n][3]);
        }
    }
}

// ---------------- RoPE on q: (t, h*128+d) -> head-major (h,t,d) ----------------
__global__ void __launch_bounds__(256) rope_q_kernel(
    const float* __restrict__ cosb, const float* __restrict__ sinb)
{
    int idx = blockIdx.x * 256 + threadIdx.x;
    if (idx >= NH * Tn * 64) return;
    int d = idx & 63;
    int t = (idx >> 6) & (Tn - 1);
    int h = idx >> 17;
    float u1 = g_tq[t * HDq + h * Dh + d];
    float u2 = g_tq[t * HDq + h * Dh + d + 64];
    float c1 = cosb[t * Dh + d],      s1 = sinb[t * Dh + d];
    float c2 = cosb[t * Dh + d + 64], s2 = sinb[t * Dh + d + 64];
    size_t o = ((size_t)h * Tn + t) * Dh + d;
    g_qh[o]      = u1 * c1 - u2 * s1;
    g_qh[o + 64] = u2 * c2 + u1 * s2;
}

// ---------------- RoPE on k + transpose v -> secondary outputs ----------------
__global__ void __launch_bounds__(256) rope_kv_kernel(
    const float* __restrict__ cosb, const float* __restrict__ sinb,
    float* __restrict__ outK, float* __restrict__ outV)
{
    int idx = blockIdx.x * 256 + threadIdx.x;
    if (idx >= NKV * Tn * 64) return;
    int d  = idx & 63;
    int t  = (idx >> 6) & (Tn - 1);
    int kh = idx >> 17;
    float u1 = g_tk[t * HDkv + kh * Dh + d];
    float u2 = g_tk[t * HDkv + kh * Dh + d + 64];
    float c1 = cosb[t * Dh + d],      s1 = sinb[t * Dh + d];
    float c2 = cosb[t * Dh + d + 64], s2 = sinb[t * Dh + d + 64];
    size_t o = ((size_t)kh * Tn + t) * Dh + d;
    outK[o]      = u1 * c1 - u2 * s1;
    outK[o + 64] = u2 * c2 + u1 * s2;
    outV[o]      = g_tv[t * HDkv + kh * Dh + d];
    outV[o + 64] = g_tv[t * HDkv + kh * Dh + d + 64];
}

// ---------------- fp32 flash attention (causal, no scaling) ----------------
#define FLASH_SMEM_FLOATS (3 * 64 * 128 + 64 * 65)
__global__ void __launch_bounds__(256) flash_kernel(
    const float* __restrict__ Kp, const float* __restrict__ Vp)
{
    extern __shared__ float smf[];
    float* qs = smf;
    float* ks = smf + 8192;
    float* vs = smf + 16384;
    float* ps = smf + 24576;

    const int tid  = threadIdx.x;
    const int quad = tid & 3;
    const int r    = tid >> 2;
    const int bq   = blockIdx.x;
    const int h    = blockIdx.y;
    const int tq0  = bq * 64;

    const float4* Q4 = (const float4*)(g_qh + ((size_t)h * Tn + tq0) * Dh);
    const float4* K4 = (const float4*)(Kp + (size_t)(h >> 2) * Tn * Dh);
    const float4* V4 = (const float4*)(Vp + (size_t)(h >> 2) * Tn * Dh);

    float4* qs4 = (float4*)qs;
    float4* ks4 = (float4*)ks;
    float4* vs4 = (float4*)vs;

#pragma unroll
    for (int i = 0; i < 8; i++) qs4[tid + 256 * i] = Q4[tid + 256 * i];

    float acc[32];
#pragma unroll
    for (int i = 0; i < 32; i++) acc[i] = 0.f;
    float mrow = -1e30f, lrow = 0.f;

    for (int j = 0; j <= bq; j++) {
        __syncthreads();
        const float4* Ksrc = K4 + (size_t)j * 64 * 32;
        const float4* Vsrc = V4 + (size_t)j * 64 * 32;
#pragma unroll
        for (int i = 0; i < 8; i++) {
            ks4[tid + 256 * i] = Ksrc[tid + 256 * i];
            vs4[tid + 256 * i] = Vsrc[tid + 256 * i];
        }
        __syncthreads();

        float sc[16];
#pragma unroll
        for (int jj = 0; jj < 16; jj++) sc[jj] = 0.f;
        const float4* qrow = (const float4*)(qs + r * Dh);
#pragma unroll 4
        for (int d4 = 0; d4 < 32; d4++) {
            float4 qv = qrow[d4];
#pragma unroll
            for (int jj = 0; jj < 16; jj++) {
                float4 kv = ks4[(quad * 16 + jj) * 32 + d4];
                sc[jj] += qv.x * kv.x + qv.y * kv.y + qv.z * kv.z + qv.w * kv.w;
            }
        }

        if (j == bq) {
#pragma unroll
            for (int jj = 0; jj < 16; jj++)
                if (quad * 16 + jj > r) sc[jj] = -1e30f;
        }

        float mloc = sc[0];
#pragma unroll
        for (int jj = 1; jj < 16; jj++) mloc = fmaxf(mloc, sc[jj]);
        mloc = fmaxf(mloc, __shfl_xor_sync(0xffffffffu, mloc, 1));
        mloc = fmaxf(mloc, __shfl_xor_sync(0xffffffffu, mloc, 2));
        float mnew  = fmaxf(mrow, mloc);
        float scale = __expf(mrow - mnew);
        float lloc = 0.f;
#pragma unroll
        for (int jj = 0; jj < 16; jj++) {
            float p = __expf(sc[jj] - mnew);
            sc[jj] = p;
            lloc += p;
        }
        lloc += __shfl_xor_sync(0xffffffffu, lloc, 1);
        lloc += __shfl_xor_sync(0xffffffffu, lloc, 2);
        lrow = lrow * scale + lloc;
        mrow = mnew;
#pragma unroll
        for (int i = 0; i < 32; i++) acc[i] *= scale;
#pragma unroll
        for (int jj = 0; jj < 16; jj++) ps[r * 65 + quad * 16 + jj] = sc[jj];
        __syncthreads();

#pragma unroll 4
        for (int s = 0; s < 64; s++) {
            float pp = ps[r * 65 + s];
            const float4* vrow = vs4 + s * 32 + quad * 8;
#pragma unroll
            for (int cc = 0; cc < 8; cc++) {
                float4 vv = vrow[cc];
                acc[cc * 4 + 0] += pp * vv.x;
                acc[cc * 4 + 1] += pp * vv.y;
                acc[cc * 4 + 2] += pp * vv.z;
                acc[cc * 4 + 3] += pp * vv.w;
            }
        }
    }

    float inv = 1.f / lrow;
    float* yrow = g_yb + (size_t)(tq0 + r) * Cdim + h * Dh + quad * 32;
#pragma unroll
    for (int cc = 0; cc < 8; cc++) {
        float4 o = make_float4(acc[cc * 4 + 0] * inv, acc[cc * 4 + 1] * inv,
                               acc[cc * 4 + 2] * inv, acc[cc * 4 + 3] * inv);
        *(float4*)(yrow + cc * 4) = o;
    }
}

// ---------------- launch ----------------
extern "C" void kernel_launch(void* const* d_in, const int* in_sizes, int n_in,
                              void* d_out, int out_size)
{
    const float* x    = (const float*)d_in[0];
    const float* Wq   = (const float*)d_in[1];
    const float* Wk   = (const float*)d_in[2];
    const float* Wv   = (const float*)d_in[3];
    const float* Wo   = (const float*)d_in[4];
    const float* cosb = (const float*)d_in[5];
    const float* sinb = (const float*)d_in[6];
    // d_in[7] = mask (reproduced exactly by causal structure; unused)

    float* out  = (float*)d_out;
    float* outY = out;
    float* outK = out + (size_t)Tn * Cdim;
    float* outV = outK + (size_t)NKV * Tn * Dh;

    float *tq, *tk, *tv, *yb;
    cudaGetSymbolAddress((void**)&tq, g_tq);
    cudaGetSymbolAddress((void**)&tk, g_tk);
    cudaGetSymbolAddress((void**)&tv, g_tv);
    cudaGetSymbolAddress((void**)&yb, g_yb);
    __nv_bfloat16 *xhi, *xlo, *ybhi, *yblo;
    __nv_bfloat16 *wqhi, *wqlo, *wkhi, *wklo, *wvhi, *wvlo, *wohi, *wolo;
    cudaGetSymbolAddress((void**)&xhi, g_xhi);
    cudaGetSymbolAddress((void**)&xlo, g_xlo);
    cudaGetSymbolAddress((void**)&ybhi, g_ybhi);
    cudaGetSymbolAddress((void**)&yblo, g_yblo);
    cudaGetSymbolAddress((void**)&wqhi, g_wqhi);
    cudaGetSymbolAddress((void**)&wqlo, g_wqlo);
    cudaGetSymbolAddress((void**)&wkhi, g_wkhi);
    cudaGetSymbolAddress((void**)&wklo, g_wklo);
    cudaGetSymbolAddress((void**)&wvhi, g_wvhi);
    cudaGetSymbolAddress((void**)&wvlo, g_wvlo);
    cudaGetSymbolAddress((void**)&wohi, g_wohi);
    cudaGetSymbolAddress((void**)&wolo, g_wolo);

    const int flash_smem = FLASH_SMEM_FLOATS * (int)sizeof(float);
    cudaFuncSetAttribute(flash_kernel, cudaFuncAttributeMaxDynamicSharedMemorySize,
                         flash_smem);
    cudaFuncSetAttribute(tcgemm_kernel, cudaFuncAttributeMaxDynamicSharedMemorySize,
                         G_SMEM);

    // 0. split/transpose prep
    split_kernel<<<(Tn * Cdim) / 256, 256>>>(x, xhi, xlo);
    tsplit_kernel<<<dim3(HDq / 32, Cdim / 32), 256>>>(Wq, wqhi, wqlo, Cdim, HDq);
    tsplit_kernel<<<dim3(HDkv / 32, Cdim / 32), 256>>>(Wk, wkhi, wklo, Cdim, HDkv);
    tsplit_kernel<<<dim3(HDkv / 32, Cdim / 32), 256>>>(Wv, wvhi, wvlo, Cdim, HDkv);
    tsplit_kernel<<<dim3(Cdim / 32, Cdim / 32), 256>>>(Wo, wohi, wolo, Cdim, Cdim);

    // 1-3. QKV projections (mma.sync split-bf16)
    tcgemm_kernel<<<dim3(HDq / 128, Tn / 128), 256, G_SMEM>>>(
        xhi, xlo, wqhi, wqlo, tq, HDq, Cdim);
    tcgemm_kernel<<<dim3(HDkv / 128, Tn / 128), 256, G_SMEM>>>(
        xhi, xlo, wkhi, wklo, tk, HDkv, Cdim);
    tcgemm_kernel<<<dim3(HDkv / 128, Tn / 128), 256, G_SMEM>>>(
        xhi, xlo, wvhi, wvlo, tv, HDkv, Cdim);

    // 4-5. RoPE + layout transforms
    rope_q_kernel<<<(NH * Tn * 64) / 256, 256>>>(cosb, sinb);
    rope_kv_kernel<<<(NKV * Tn * 64) / 256, 256>>>(cosb, sinb, outK, outV);

    // 6. causal flash attention
    flash_kernel<<<dim3(Tn / 64, NH), 256, flash_smem>>>(outK, outV);

    // 7. output projection
    split_kernel<<<(Tn * Cdim) / 256, 256>>>(yb, ybhi, yblo);
    tcgemm_kernel<<<dim3(Cdim / 128, Tn / 128), 256, G_SMEM>>>(
        ybhi, yblo, wohi, wolo, outY, Cdim, Cdim);
}

// round 4
// speedup vs baseline: 6.5933x; 5.4465x over previous
#include <cuda_runtime.h>
#include <cuda_bf16.h>
#include <cstdint>

// Problem constants
#define Tn   2048
#define Cdim 4096
#define NH   32
#define NKV  8
#define Dh   128
#define HDq  (NH*Dh)    // 4096
#define HDkv (NKV*Dh)   // 1024

// ---------------- scratch (device globals; no allocation) ----------------
__device__ __align__(256) float g_tq[Tn * HDq];
__device__ __align__(256) float g_tk[Tn * HDkv];
__device__ __align__(256) float g_tv[Tn * HDkv];

__device__ __align__(256) __nv_bfloat16 g_xhi[Tn * Cdim];
__device__ __align__(256) __nv_bfloat16 g_xlo[Tn * Cdim];
__device__ __align__(256) __nv_bfloat16 g_ybhi[Tn * Cdim];
__device__ __align__(256) __nv_bfloat16 g_yblo[Tn * Cdim];
__device__ __align__(256) __nv_bfloat16 g_qhi[(size_t)NH * Tn * Dh];
__device__ __align__(256) __nv_bfloat16 g_qlo[(size_t)NH * Tn * Dh];
__device__ __align__(256) __nv_bfloat16 g_khi[(size_t)NKV * Tn * Dh];
__device__ __align__(256) __nv_bfloat16 g_klo[(size_t)NKV * Tn * Dh];
__device__ __align__(256) __nv_bfloat16 g_vhi[(size_t)NKV * Tn * Dh];
__device__ __align__(256) __nv_bfloat16 g_vlo[(size_t)NKV * Tn * Dh];
__device__ __align__(256) __nv_bfloat16 g_wqhi[(size_t)HDq * Cdim];
__device__ __align__(256) __nv_bfloat16 g_wqlo[(size_t)HDq * Cdim];
__device__ __align__(256) __nv_bfloat16 g_wkhi[(size_t)HDkv * Cdim];
__device__ __align__(256) __nv_bfloat16 g_wklo[(size_t)HDkv * Cdim];
__device__ __align__(256) __nv_bfloat16 g_wvhi[(size_t)HDkv * Cdim];
__device__ __align__(256) __nv_bfloat16 g_wvlo[(size_t)HDkv * Cdim];
__device__ __align__(256) __nv_bfloat16 g_wohi[(size_t)Cdim * Cdim];
__device__ __align__(256) __nv_bfloat16 g_wolo[(size_t)Cdim * Cdim];

// ---------------- baseline-ISA helpers (sm_80+ PTX only) ----------------
__device__ __forceinline__ uint32_t smem_u32(const void* p) {
    uint32_t a;
    asm("{ .reg .u64 t; cvta.to.shared.u64 t, %1; cvt.u32.u64 %0, t; }" : "=r"(a) : "l"(p));
    return a;
}

#define CP_ASYNC16(sm, gp) \
    asm volatile("cp.async.cg.shared.global [%0], [%1], 16;" :: "r"(sm), "l"(gp) : "memory")
#define CP_COMMIT() asm volatile("cp.async.commit_group;" ::: "memory")
#define CP_WAIT(n)  asm volatile("cp.async.wait_group %0;" :: "n"(n) : "memory")

__device__ __forceinline__ void ldsm4(uint32_t* r, uint32_t addr) {
    asm volatile("ldmatrix.sync.aligned.m8n8.x4.shared.b16 {%0,%1,%2,%3}, [%4];"
        : "=r"(r[0]), "=r"(r[1]), "=r"(r[2]), "=r"(r[3]) : "r"(addr));
}
__device__ __forceinline__ void ldsm4t(uint32_t* r, uint32_t addr) {
    asm volatile("ldmatrix.sync.aligned.m8n8.x4.trans.shared.b16 {%0,%1,%2,%3}, [%4];"
        : "=r"(r[0]), "=r"(r[1]), "=r"(r[2]), "=r"(r[3]) : "r"(addr));
}

__device__ __forceinline__ void mma_bf16(float* c, const uint32_t* a, const uint32_t* b) {
    asm volatile(
        "mma.sync.aligned.m16n8k16.row.col.f32.bf16.bf16.f32 "
        "{%0,%1,%2,%3}, {%4,%5,%6,%7}, {%8,%9}, {%0,%1,%2,%3};"
        : "+f"(c[0]), "+f"(c[1]), "+f"(c[2]), "+f"(c[3])
        : "r"(a[0]), "r"(a[1]), "r"(a[2]), "r"(a[3]), "r"(b[0]), "r"(b[1]));
}

__device__ __forceinline__ void split2(float a, float b, uint32_t& hi, uint32_t& lo) {
    __nv_bfloat16 ah = __float2bfloat16(a), bh = __float2bfloat16(b);
    __nv_bfloat162 H; H.x = ah; H.y = bh;
    __nv_bfloat162 L;
    L.x = __float2bfloat16(a - __bfloat162float(ah));
    L.y = __float2bfloat16(b - __bfloat162float(bh));
    hi = *reinterpret_cast<uint32_t*>(&H);
    lo = *reinterpret_cast<uint32_t*>(&L);
}

// ---------------- split x (fp32 -> hi/lo bf16) ----------------
__global__ void __launch_bounds__(256) split_kernel(
    const float* __restrict__ X, __nv_bfloat16* __restrict__ hi,
    __nv_bfloat16* __restrict__ lo)
{
    int idx = blockIdx.x * 256 + threadIdx.x;
    float v = X[idx];
    __nv_bfloat16 h = __float2bfloat16(v);
    hi[idx] = h;
    lo[idx] = __float2bfloat16(v - __bfloat162float(h));
}

// ---------------- transpose+split W [K,N] fp32 -> [N,K] hi/lo bf16 ----------------
__global__ void __launch_bounds__(256) tsplit_kernel(
    const float* __restrict__ W, __nv_bfloat16* __restrict__ Thi,
    __nv_bfloat16* __restrict__ Tlo, int K, int N)
{
    __shared__ float tile[32][33];
    int n0 = blockIdx.x * 32, k0 = blockIdx.y * 32;
    int tx = threadIdx.x & 31, ty = threadIdx.x >> 5;
#pragma unroll
    for (int j = 0; j < 4; j++)
        tile[ty + 8 * j][tx] = W[(size_t)(k0 + ty + 8 * j) * N + n0 + tx];
    __syncthreads();
#pragma unroll
    for (int j = 0; j < 4; j++) {
        int n = ty + 8 * j;
        float v = tile[tx][n];
        __nv_bfloat16 h = __float2bfloat16(v);
        __nv_bfloat16 l = __float2bfloat16(v - __bfloat162float(h));
        size_t o = (size_t)(n0 + n) * K + k0 + tx;
        Thi[o] = h;
        Tlo[o] = l;
    }
}

// ---------------- mma.sync split-bf16 GEMM ----------------
#define PITCH   80
#define T_A     10240
#define T_STAGE (4 * T_A)
#define G_SMEM  (2 * T_STAGE)

__device__ __forceinline__ void g_load_pair(
    uint32_t sbase, const __nv_bfloat16* __restrict__ hi,
    const __nv_bfloat16* __restrict__ lo, int rbase, int kc, int K, int tid)
{
#pragma unroll
    for (int i = 0; i < 2; i++) {
        int s = tid + 256 * i;
        int row = s >> 2, part = s & 3;
        size_t go = (size_t)(rbase + row) * K + (size_t)kc * 32 + part * 8;
        uint32_t so = (uint32_t)(row * PITCH + part * 16);
        CP_ASYNC16(sbase + so, hi + go);
        CP_ASYNC16(sbase + T_A + so, lo + go);
    }
}

__global__ void __launch_bounds__(256) tcgemm_kernel(
    const __nv_bfloat16* __restrict__ Ahi, const __nv_bfloat16* __restrict__ Alo,
    const __nv_bfloat16* __restrict__ Bhi, const __nv_bfloat16* __restrict__ Blo,
    float* __restrict__ C, int N, int K)
{
    extern __shared__ char smc[];
    const uint32_t sb0 = smem_u32(smc);
    const int tid  = threadIdx.x;
    const int lane = tid & 31;
    const int wid  = tid >> 5;
    const int wm   = wid & 1;
    const int wn   = wid >> 1;
    const int row0 = blockIdx.y * 128;
    const int col0 = blockIdx.x * 128;

    float acc[4][4][4];
#pragma unroll
    for (int m = 0; m < 4; m++)
#pragma unroll
        for (int n = 0; n < 4; n++)
#pragma unroll
            for (int e = 0; e < 4; e++) acc[m][n][e] = 0.f;

    const uint32_t a_row = (uint32_t)(wm * 64 + (lane & 15));
    const uint32_t a_kb  = (uint32_t)((lane >> 4) * 16);
    const int bmat = lane >> 3, bwin = lane & 7;
    const uint32_t b_n  = (uint32_t)(wn * 32 + bwin + (bmat >> 1) * 8);
    const uint32_t b_kb = (uint32_t)((bmat & 1) * 16);

    const int nk = K >> 5;

    g_load_pair(sb0,           Ahi, Alo, row0, 0, K, tid);
    g_load_pair(sb0 + 2 * T_A, Bhi, Blo, col0, 0, K, tid);
    CP_COMMIT();

    for (int kc = 0; kc < nk; kc++) {
        uint32_t sb = sb0 + (uint32_t)(kc & 1) * T_STAGE;
        if (kc + 1 < nk) {
            uint32_t sb2 = sb0 + (uint32_t)((kc + 1) & 1) * T_STAGE;
            g_load_pair(sb2,           Ahi, Alo, row0, kc + 1, K, tid);
            g_load_pair(sb2 + 2 * T_A, Bhi, Blo, col0, kc + 1, K, tid);
            CP_COMMIT();
            CP_WAIT(1);
        } else {
            CP_WAIT(0);
        }
        __syncthreads();

        const uint32_t aB = sb + a_row * PITCH + a_kb;
        const uint32_t bB = sb + 2 * T_A + b_n * PITCH + b_kb;

#pragma unroll
        for (int ks = 0; ks < 2; ks++) {
            uint32_t ah[4][4], al[4][4], bh[2][4], bl[2][4];
#pragma unroll
            for (int m = 0; m < 4; m++) {
                ldsm4(ah[m], aB + (uint32_t)(m * 16 * PITCH) + ks * 32);
                ldsm4(al[m], aB + T_A + (uint32_t)(m * 16 * PITCH) + ks * 32);
            }
#pragma unroll
            for (int p = 0; p < 2; p++) {
                ldsm4(bh[p], bB + (uint32_t)(p * 16 * PITCH) + ks * 32);
                ldsm4(bl[p], bB + T_A + (uint32_t)(p * 16 * PITCH) + ks * 32);
            }
#pragma unroll
            for (int m = 0; m < 4; m++)
#pragma unroll
                for (int p = 0; p < 2; p++)
#pragma unroll
                    for (int h = 0; h < 2; h++) {
                        float* c = acc[m][p * 2 + h];
                        uint32_t bhh[2] = {bh[p][h * 2], bh[p][h * 2 + 1]};
                        uint32_t bll[2] = {bl[p][h * 2], bl[p][h * 2 + 1]};
                        mma_bf16(c, ah[m], bhh);
                        mma_bf16(c, ah[m], bll);
                        mma_bf16(c, al[m], bhh);
                    }
        }
        __syncthreads();
    }

    const int g = lane >> 2, t = lane & 3;
#pragma unroll
    for (int m = 0; m < 4; m++) {
        int r0 = row0 + wm * 64 + m * 16 + g;
#pragma unroll
        for (int n = 0; n < 4; n++) {
            int c = col0 + wn * 32 + n * 8 + 2 * t;
            *(float2*)&C[(size_t)r0 * N + c] = make_float2(acc[m][n][0], acc[m][n][1]);
            *(float2*)&C[(size_t)(r0 + 8) * N + c] = make_float2(acc[m][n][2], acc[m][n][3]);
        }
    }
}

// ---------------- RoPE on q -> head-major hi/lo bf16 ----------------
__global__ void __launch_bounds__(256) rope_q_kernel(
    const float* __restrict__ cosb, const float* __restrict__ sinb)
{
    int idx = blockIdx.x * 256 + threadIdx.x;
    if (idx >= NH * Tn * 64) return;
    int d = idx & 63;
    int t = (idx >> 6) & (Tn - 1);
    int h = idx >> 17;
    float u1 = g_tq[t * HDq + h * Dh + d];
    float u2 = g_tq[t * HDq + h * Dh + d + 64];
    float c1 = cosb[t * Dh + d],      s1 = sinb[t * Dh + d];
    float c2 = cosb[t * Dh + d + 64], s2 = sinb[t * Dh + d + 64];
    float y1 = u1 * c1 - u2 * s1;
    float y2 = u2 * c2 + u1 * s2;
    size_t o = ((size_t)h * Tn + t) * Dh + d;
    __nv_bfloat16 h1 = __float2bfloat16(y1), h2 = __float2bfloat16(y2);
    g_qhi[o]      = h1;
    g_qlo[o]      = __float2bfloat16(y1 - __bfloat162float(h1));
    g_qhi[o + 64] = h2;
    g_qlo[o + 64] = __float2bfloat16(y2 - __bfloat162float(h2));
}

// ---------------- RoPE on k + v -> hi/lo bf16 + fp32 secondary outputs ----------------
__global__ void __launch_bounds__(256) rope_kv_kernel(
    const float* __restrict__ cosb, const float* __restrict__ sinb,
    float* __restrict__ outK, float* __restrict__ outV)
{
    int idx = blockIdx.x * 256 + threadIdx.x;
    if (idx >= NKV * Tn * 64) return;
    int d  = idx & 63;
    int t  = (idx >> 6) & (Tn - 1);
    int kh = idx >> 17;
    float u1 = g_tk[t * HDkv + kh * Dh + d];
    float u2 = g_tk[t * HDkv + kh * Dh + d + 64];
    float c1 = cosb[t * Dh + d],      s1 = sinb[t * Dh + d];
    float c2 = cosb[t * Dh + d + 64], s2 = sinb[t * Dh + d + 64];
    float y1 = u1 * c1 - u2 * s1;
    float y2 = u2 * c2 + u1 * s2;
    size_t o = ((size_t)kh * Tn + t) * Dh + d;
    outK[o]      = y1;
    outK[o + 64] = y2;
    __nv_bfloat16 h1 = __float2bfloat16(y1), h2 = __float2bfloat16(y2);
    g_khi[o]      = h1;
    g_klo[o]      = __float2bfloat16(y1 - __bfloat162float(h1));
    g_khi[o + 64] = h2;
    g_klo[o + 64] = __float2bfloat16(y2 - __bfloat162float(h2));
    float v1 = g_tv[t * HDkv + kh * Dh + d];
    float v2 = g_tv[t * HDkv + kh * Dh + d + 64];
    outV[o]      = v1;
    outV[o + 64] = v2;
    __nv_bfloat16 g1 = __float2bfloat16(v1), g2 = __float2bfloat16(v2);
    g_vhi[o]      = g1;
    g_vlo[o]      = __float2bfloat16(v1 - __bfloat162float(g1));
    g_vhi[o + 64] = g2;
    g_vlo[o + 64] = __float2bfloat16(v2 - __bfloat162float(g2));
}

// ---------------- flash attention via mma.sync (split-bf16, causal) ----------------
// BM=128, BN=64. 8 warps, each owns 16 rows full width. grid (16, NH), 256 thr.
#define FP272   272
#define QTILE   (128 * FP272)          // 34816
#define KTILE   (64 * FP272)           // 17408
#define FSTAGE  (4 * KTILE)            // Kh,Kl,Vh,Vl = 69632
#define F_SMEM  (2 * QTILE + 2 * FSTAGE)  // 208896

__device__ __forceinline__ void f_load_kv(
    uint32_t st, const __nv_bfloat16* __restrict__ kh, const __nv_bfloat16* __restrict__ kl,
    const __nv_bfloat16* __restrict__ vh, const __nv_bfloat16* __restrict__ vl, int tid)
{
#pragma unroll
    for (int i = 0; i < 4; i++) {
        int s = tid + 256 * i;             // 1024 chunks of 16B per tile
        int r = s >> 4, c = s & 15;
        uint32_t so = (uint32_t)(r * FP272 + c * 16);
        size_t go = (size_t)r * Dh + c * 8;
        CP_ASYNC16(st + so,             kh + go);
        CP_ASYNC16(st + KTILE + so,     kl + go);
        CP_ASYNC16(st + 2 * KTILE + so, vh + go);
        CP_ASYNC16(st + 3 * KTILE + so, vl + go);
    }
}

__global__ void __launch_bounds__(256) flash_mma_kernel(
    __nv_bfloat16* __restrict__ ybhi, __nv_bfloat16* __restrict__ yblo)
{
    extern __shared__ char smc[];
    const uint32_t sb = smem_u32(smc);
    const int tid = threadIdx.x, lane = tid & 31, w = tid >> 5;
    const int h  = blockIdx.y;
    const int qi = (int)gridDim.x - 1 - (int)blockIdx.x;   // big tiles first
    const int q0 = qi * 128;
    const int kvh = h >> 2;
    const int nb = 2 * qi + 2;

    const uint32_t sQh = sb, sQl = sb + QTILE;
    const uint32_t sKV = sb + 2 * QTILE;

    // per-lane ldmatrix address components
    const uint32_t aQoff = (uint32_t)((16 * w + (lane & 15)) * FP272 + (lane >> 4) * 16);
    const int bmat = lane >> 3, bwin = lane & 7;
    const uint32_t bKoff = (uint32_t)((bwin + ((bmat >> 1) << 3)) * FP272 + ((bmat & 1) << 4));
    const uint32_t bVoff = (uint32_t)((lane & 15) * FP272 + ((lane >> 4) << 4));

    // loads: Q (whole CTA tile) + KV block 0 into stage 0
    {
        const __nv_bfloat16* gqh = g_qhi + ((size_t)h * Tn + q0) * Dh;
        const __nv_bfloat16* gql = g_qlo + ((size_t)h * Tn + q0) * Dh;
#pragma unroll
        for (int i = 0; i < 8; i++) {
            int s = tid + 256 * i;          // 2048 chunks
            int r = s >> 4, c = s & 15;
            uint32_t so = (uint32_t)(r * FP272 + c * 16);
            size_t go = (size_t)r * Dh + c * 8;
            CP_ASYNC16(sQh + so, gqh + go);
            CP_ASYNC16(sQl + so, gql + go);
        }
        f_load_kv(sKV, g_khi + (size_t)kvh * Tn * Dh, g_klo + (size_t)kvh * Tn * Dh,
                  g_vhi + (size_t)kvh * Tn * Dh, g_vlo + (size_t)kvh * Tn * Dh, tid);
        CP_COMMIT();
    }

    float o[16][4];
#pragma unroll
    for (int dt = 0; dt < 16; dt++)
#pragma unroll
        for (int e = 0; e < 4; e++) o[dt][e] = 0.f;
    float m0 = -1e30f, m1 = -1e30f, l0 = 0.f, l1 = 0.f;

    const int row_lo = q0 + 16 * w + (lane >> 2);
    const int row_hi = row_lo + 8;

    for (int j = 0; j < nb; j++) {
        if (j + 1 < nb) {
            size_t kb = (size_t)(j + 1) * 64;
            uint32_t st2 = sKV + (uint32_t)((j + 1) & 1) * FSTAGE;
            f_load_kv(st2,
                      g_khi + ((size_t)kvh * Tn + kb) * Dh, g_klo + ((size_t)kvh * Tn + kb) * Dh,
                      g_vhi + ((size_t)kvh * Tn + kb) * Dh, g_vlo + ((size_t)kvh * Tn + kb) * Dh,
                      tid);
            CP_COMMIT();
            CP_WAIT(1);
        } else {
            CP_WAIT(0);
        }
        __syncthreads();   // stage j visible to all

        const uint32_t stg = sKV + (uint32_t)(j & 1) * FSTAGE;
        const int kb0 = j * 64;
        const bool active = (q0 + 16 * w + 15) >= kb0;

        if (active) {
            // ---- S = Qhi*Khi^T + Qhi*Klo^T + Qlo*Khi^T ----
            float sc[8][4];
#pragma unroll
            for (int nt = 0; nt < 8; nt++)
#pragma unroll
                for (int e = 0; e < 4; e++) sc[nt][e] = 0.f;

#pragma unroll
            for (int ks = 0; ks < 8; ks++) {
                uint32_t qh_f[4], ql_f[4];
                ldsm4(qh_f, sQh + aQoff + ks * 32);
                ldsm4(ql_f, sQl + aQoff + ks * 32);
#pragma unroll
                for (int p = 0; p < 4; p++) {
                    uint32_t khf[4], klf[4];
                    uint32_t ka = stg + bKoff + (uint32_t)(p * 16 * FP272) + ks * 32;
                    ldsm4(khf, ka);
                    ldsm4(klf, ka + KTILE);
#pragma unroll
                    for (int hh = 0; hh < 2; hh++) {
                        float* c = sc[p * 2 + hh];
                        uint32_t bh2[2] = {khf[hh * 2], khf[hh * 2 + 1]};
                        uint32_t bl2[2] = {klf[hh * 2], klf[hh * 2 + 1]};
                        mma_bf16(c, qh_f, bh2);
                        mma_bf16(c, qh_f, bl2);
                        mma_bf16(c, ql_f, bh2);
                    }
                }
            }

            // ---- causal mask ----
            if (kb0 + 63 > row_lo) {
#pragma unroll
                for (int nt = 0; nt < 8; nt++) {
                    int col = kb0 + nt * 8 + 2 * (lane & 3);
                    if (col > row_lo)     sc[nt][0] = -1e30f;
                    if (col + 1 > row_lo) sc[nt][1] = -1e30f;
                    if (col > row_hi)     sc[nt][2] = -1e30f;
                    if (col + 1 > row_hi) sc[nt][3] = -1e30f;
                }
            }

            // ---- online softmax ----
            float ml0 = -1e30f, ml1 = -1e30f;
#pragma unroll
            for (int nt = 0; nt < 8; nt++) {
                ml0 = fmaxf(ml0, fmaxf(sc[nt][0], sc[nt][1]));
                ml1 = fmaxf(ml1, fmaxf(sc[nt][2], sc[nt][3]));
            }
            ml0 = fmaxf(ml0, __shfl_xor_sync(0xffffffffu, ml0, 1));
            ml0 = fmaxf(ml0, __shfl_xor_sync(0xffffffffu, ml0, 2));
            ml1 = fmaxf(ml1, __shfl_xor_sync(0xffffffffu, ml1, 1));
            ml1 = fmaxf(ml1, __shfl_xor_sync(0xffffffffu, ml1, 2));
            float mn0 = fmaxf(m0, ml0), mn1 = fmaxf(m1, ml1);
            float es0 = __expf(m0 - mn0), es1 = __expf(m1 - mn1);
            float ls0 = 0.f, ls1 = 0.f;
#pragma unroll
            for (int nt = 0; nt < 8; nt++) {
                sc[nt][0] = __expf(sc[nt][0] - mn0);
                sc[nt][1] = __expf(sc[nt][1] - mn0);
                sc[nt][2] = __expf(sc[nt][2] - mn1);
                sc[nt][3] = __expf(sc[nt][3] - mn1);
                ls0 += sc[nt][0] + sc[nt][1];
                ls1 += sc[nt][2] + sc[nt][3];
            }
            ls0 += __shfl_xor_sync(0xffffffffu, ls0, 1);
            ls0 += __shfl_xor_sync(0xffffffffu, ls0, 2);
            ls1 += __shfl_xor_sync(0xffffffffu, ls1, 1);
            ls1 += __shfl_xor_sync(0xffffffffu, ls1, 2);
            l0 = l0 * es0 + ls0;  m0 = mn0;
            l1 = l1 * es1 + ls1;  m1 = mn1;
#pragma unroll
            for (int dt = 0; dt < 16; dt++) {
                o[dt][0] *= es0;  o[dt][1] *= es0;
                o[dt][2] *= es1;  o[dt][3] *= es1;
            }

            // ---- O += P * V (split-bf16, V^T via ldmatrix.trans) ----
#pragma unroll
            for (int j2 = 0; j2 < 4; j2++) {
                uint32_t ph[4], pl[4];
                split2(sc[2 * j2][0],     sc[2 * j2][1],     ph[0], pl[0]);
                split2(sc[2 * j2][2],     sc[2 * j2][3],     ph[1], pl[1]);
                split2(sc[2 * j2 + 1][0], sc[2 * j2 + 1][1], ph[2], pl[2]);
                split2(sc[2 * j2 + 1][2], sc[2 * j2 + 1][3], ph[3], pl[3]);
#pragma unroll
                for (int dt2 = 0; dt2 < 8; dt2++) {
                    uint32_t vhf[4], vlf[4];
                    uint32_t va = stg + 2 * KTILE + bVoff +
                                  (uint32_t)(j2 * 16 * FP272) + (uint32_t)(dt2 * 32);
                    ldsm4t(vhf, va);
                    ldsm4t(vlf, va + KTILE);
#pragma unroll
                    for (int hf = 0; hf < 2; hf++) {
                        float* c = o[dt2 * 2 + hf];
                        uint32_t bh2[2] = {vhf[hf * 2], vhf[hf * 2 + 1]};
                        uint32_t bl2[2] = {vlf[hf * 2], vlf[hf * 2 + 1]};
                        mma_bf16(c, ph, bh2);
                        mma_bf16(c, ph, bl2);
                        mma_bf16(c, pl, bh2);
                    }
                }
            }
        }
        __syncthreads();   // everyone done reading stage j before it is overwritten
    }

    // ---- epilogue: y hi/lo bf16 directly for the Wo GEMM ----
    float inv0 = 1.f / l0, inv1 = 1.f / l1;
#pragma unroll
    for (int dt = 0; dt < 16; dt++) {
        int d = dt * 8 + 2 * (lane & 3);
        size_t o0 = (size_t)row_lo * Cdim + h * Dh + d;
        size_t o1 = (size_t)row_hi * Cdim + h * Dh + d;
        uint32_t hi0, lo0, hi1, lo1;
        split2(o[dt][0] * inv0, o[dt][1] * inv0, hi0, lo0);
        split2(o[dt][2] * inv1, o[dt][3] * inv1, hi1, lo1);
        *reinterpret_cast<uint32_t*>(ybhi + o0) = hi0;
        *reinterpret_cast<uint32_t*>(yblo + o0) = lo0;
        *reinterpret_cast<uint32_t*>(ybhi + o1) = hi1;
        *reinterpret_cast<uint32_t*>(yblo + o1) = lo1;
    }
}

// ---------------- launch ----------------
extern "C" void kernel_launch(void* const* d_in, const int* in_sizes, int n_in,
                              void* d_out, int out_size)
{
    const float* x    = (const float*)d_in[0];
    const float* Wq   = (const float*)d_in[1];
    const float* Wk   = (const float*)d_in[2];
    const float* Wv   = (const float*)d_in[3];
    const float* Wo   = (const float*)d_in[4];
    const float* cosb = (const float*)d_in[5];
    const float* sinb = (const float*)d_in[6];
    // d_in[7] = mask (reproduced exactly by causal structure; unused)

    float* out  = (float*)d_out;
    float* outY = out;
    float* outK = out + (size_t)Tn * Cdim;
    float* outV = outK + (size_t)NKV * Tn * Dh;

    float *tq, *tk, *tv;
    cudaGetSymbolAddress((void**)&tq, g_tq);
    cudaGetSymbolAddress((void**)&tk, g_tk);
    cudaGetSymbolAddress((void**)&tv, g_tv);
    __nv_bfloat16 *xhi, *xlo, *ybhi, *yblo;
    __nv_bfloat16 *wqhi, *wqlo, *wkhi, *wklo, *wvhi, *wvlo, *wohi, *wolo;
    cudaGetSymbolAddress((void**)&xhi, g_xhi);
    cudaGetSymbolAddress((void**)&xlo, g_xlo);
    cudaGetSymbolAddress((void**)&ybhi, g_ybhi);
    cudaGetSymbolAddress((void**)&yblo, g_yblo);
    cudaGetSymbolAddress((void**)&wqhi, g_wqhi);
    cudaGetSymbolAddress((void**)&wqlo, g_wqlo);
    cudaGetSymbolAddress((void**)&wkhi, g_wkhi);
    cudaGetSymbolAddress((void**)&wklo, g_wklo);
    cudaGetSymbolAddress((void**)&wvhi, g_wvhi);
    cudaGetSymbolAddress((void**)&wvlo, g_wvlo);
    cudaGetSymbolAddress((void**)&wohi, g_wohi);
    cudaGetSymbolAddress((void**)&wolo, g_wolo);

    cudaFuncSetAttribute(tcgemm_kernel, cudaFuncAttributeMaxDynamicSharedMemorySize,
                         G_SMEM);
    cudaFuncSetAttribute(flash_mma_kernel, cudaFuncAttributeMaxDynamicSharedMemorySize,
                         F_SMEM);

    // 0. split/transpose prep
    split_kernel<<<(Tn * Cdim) / 256, 256>>>(x, xhi, xlo);
    tsplit_kernel<<<dim3(HDq / 32, Cdim / 32), 256>>>(Wq, wqhi, wqlo, Cdim, HDq);
    tsplit_kernel<<<dim3(HDkv / 32, Cdim / 32), 256>>>(Wk, wkhi, wklo, Cdim, HDkv);
    tsplit_kernel<<<dim3(HDkv / 32, Cdim / 32), 256>>>(Wv, wvhi, wvlo, Cdim, HDkv);
    tsplit_kernel<<<dim3(Cdim / 32, Cdim / 32), 256>>>(Wo, wohi, wolo, Cdim, Cdim);

    // 1-3. QKV projections
    tcgemm_kernel<<<dim3(HDq / 128, Tn / 128), 256, G_SMEM>>>(
        xhi, xlo, wqhi, wqlo, tq, HDq, Cdim);
    tcgemm_kernel<<<dim3(HDkv / 128, Tn / 128), 256, G_SMEM>>>(
        xhi, xlo, wkhi, wklo, tk, HDkv, Cdim);
    tcgemm_kernel<<<dim3(HDkv / 128, Tn / 128), 256, G_SMEM>>>(
        xhi, xlo, wvhi, wvlo, tv, HDkv, Cdim);

    // 4-5. RoPE + hi/lo conversion (k/v fp32 copies are final outputs)
    rope_q_kernel<<<(NH * Tn * 64) / 256, 256>>>(cosb, sinb);
    rope_kv_kernel<<<(NKV * Tn * 64) / 256, 256>>>(cosb, sinb, outK, outV);

    // 6. causal flash attention (tensor cores)
    flash_mma_kernel<<<dim3(Tn / 128, NH), 256, F_SMEM>>>(ybhi, yblo);

    // 7. output projection
    tcgemm_kernel<<<dim3(Cdim / 128, Tn / 128), 256, G_SMEM>>>(
        ybhi, yblo, wohi, wolo, outY, Cdim, Cdim);
}

// round 5
// speedup vs baseline: 7.7286x; 1.1722x over previous
#include <cuda_runtime.h>
#include <cuda_bf16.h>
#include <cuda_fp16.h>
#include <cstdint>

// Problem constants
#define Tn   2048
#define Cdim 4096
#define NH   32
#define NKV  8
#define Dh   128
#define HDq  (NH*Dh)    // 4096
#define HDkv (NKV*Dh)   // 1024
#define HD2  (2*HDkv)   // 2048 (merged K|V)

// ---------------- scratch (device globals; no allocation) ----------------
__device__ __align__(256) float g_tq[Tn * HDq];
__device__ __align__(256) float g_tkv[Tn * HD2];

__device__ __align__(256) __nv_bfloat16 g_xhi[Tn * Cdim];
__device__ __align__(256) __nv_bfloat16 g_xlo[Tn * Cdim];
__device__ __align__(256) __nv_bfloat16 g_qhi[(size_t)NH * Tn * Dh];
__device__ __align__(256) __nv_bfloat16 g_qlo[(size_t)NH * Tn * Dh];
__device__ __align__(256) __nv_bfloat16 g_khi[(size_t)NKV * Tn * Dh];
__device__ __align__(256) __nv_bfloat16 g_klo[(size_t)NKV * Tn * Dh];
__device__ __align__(256) __half       g_vh [(size_t)NKV * Tn * Dh];
__device__ __align__(256) __half       g_ybhi[Tn * Cdim];
__device__ __align__(256) __half       g_yblo[Tn * Cdim];
__device__ __align__(256) __nv_bfloat16 g_wqhi[(size_t)HDq * Cdim];
__device__ __align__(256) __nv_bfloat16 g_wqlo[(size_t)HDq * Cdim];
__device__ __align__(256) __nv_bfloat16 g_wkvhi[(size_t)HD2 * Cdim];
__device__ __align__(256) __nv_bfloat16 g_wkvlo[(size_t)HD2 * Cdim];
__device__ __align__(256) __half       g_wohi[(size_t)Cdim * Cdim];

// ---------------- baseline-ISA helpers (sm_80+ PTX only) ----------------
__device__ __forceinline__ uint32_t smem_u32(const void* p) {
    uint32_t a;
    asm("{ .reg .u64 t; cvta.to.shared.u64 t, %1; cvt.u32.u64 %0, t; }" : "=r"(a) : "l"(p));
    return a;
}

#define CP_ASYNC16(sm, gp) \
    asm volatile("cp.async.cg.shared.global [%0], [%1], 16;" :: "r"(sm), "l"(gp) : "memory")
#define CP_COMMIT() asm volatile("cp.async.commit_group;" ::: "memory")
#define CP_WAIT(n)  asm volatile("cp.async.wait_group %0;" :: "n"(n) : "memory")

__device__ __forceinline__ void ldsm4(uint32_t* r, uint32_t addr) {
    asm volatile("ldmatrix.sync.aligned.m8n8.x4.shared.b16 {%0,%1,%2,%3}, [%4];"
        : "=r"(r[0]), "=r"(r[1]), "=r"(r[2]), "=r"(r[3]) : "r"(addr));
}
__device__ __forceinline__ void ldsm4t(uint32_t* r, uint32_t addr) {
    asm volatile("ldmatrix.sync.aligned.m8n8.x4.trans.shared.b16 {%0,%1,%2,%3}, [%4];"
        : "=r"(r[0]), "=r"(r[1]), "=r"(r[2]), "=r"(r[3]) : "r"(addr));
}

__device__ __forceinline__ void mma_bf16(float* c, const uint32_t* a, const uint32_t* b) {
    asm volatile(
        "mma.sync.aligned.m16n8k16.row.col.f32.bf16.bf16.f32 "
        "{%0,%1,%2,%3}, {%4,%5,%6,%7}, {%8,%9}, {%0,%1,%2,%3};"
        : "+f"(c[0]), "+f"(c[1]), "+f"(c[2]), "+f"(c[3])
        : "r"(a[0]), "r"(a[1]), "r"(a[2]), "r"(a[3]), "r"(b[0]), "r"(b[1]));
}
__device__ __forceinline__ void mma_f16(float* c, const uint32_t* a, const uint32_t* b) {
    asm volatile(
        "mma.sync.aligned.m16n8k16.row.col.f32.f16.f16.f32 "
        "{%0,%1,%2,%3}, {%4,%5,%6,%7}, {%8,%9}, {%0,%1,%2,%3};"
        : "+f"(c[0]), "+f"(c[1]), "+f"(c[2]), "+f"(c[3])
        : "r"(a[0]), "r"(a[1]), "r"(a[2]), "r"(a[3]), "r"(b[0]), "r"(b[1]));
}

// fp16 hi/lo split of a float pair
__device__ __forceinline__ void split2h(float a, float b, uint32_t& hi, uint32_t& lo) {
    __half2 H = __floats2half2_rn(a, b);
    float ra = a - __half2float(__low2half(H));
    float rb = b - __half2float(__high2half(H));
    __half2 L = __floats2half2_rn(ra, rb);
    hi = *reinterpret_cast<uint32_t*>(&H);
    lo = *reinterpret_cast<uint32_t*>(&L);
}

// ---------------- split x (fp32 -> hi/lo bf16) ----------------
__global__ void __launch_bounds__(256) split_kernel(
    const float* __restrict__ X, __nv_bfloat16* __restrict__ hi,
    __nv_bfloat16* __restrict__ lo)
{
    int idx = blockIdx.x * 256 + threadIdx.x;
    float v = X[idx];
    __nv_bfloat16 h = __float2bfloat16(v);
    hi[idx] = h;
    lo[idx] = __float2bfloat16(v - __bfloat162float(h));
}

// ---------------- transpose+split W [K,N] fp32 -> [N,K] hi/lo bf16 ----------------
__global__ void __launch_bounds__(256) tsplit_kernel(
    const float* __restrict__ W, __nv_bfloat16* __restrict__ Thi,
    __nv_bfloat16* __restrict__ Tlo, int K, int N)
{
    __shared__ float tile[32][33];
    int n0 = blockIdx.x * 32, k0 = blockIdx.y * 32;
    int tx = threadIdx.x & 31, ty = threadIdx.x >> 5;
#pragma unroll
    for (int j = 0; j < 4; j++)
        tile[ty + 8 * j][tx] = W[(size_t)(k0 + ty + 8 * j) * N + n0 + tx];
    __syncthreads();
#pragma unroll
    for (int j = 0; j < 4; j++) {
        int n = ty + 8 * j;
        float v = tile[tx][n];
        __nv_bfloat16 h = __float2bfloat16(v);
        __nv_bfloat16 l = __float2bfloat16(v - __bfloat162float(h));
        size_t o = (size_t)(n0 + n) * K + k0 + tx;
        Thi[o] = h;
        Tlo[o] = l;
    }
}

// ---------------- transpose W [K,N] fp32 -> [N,K] fp16 (hi only) ----------------
__global__ void __launch_bounds__(256) tsplit_h_kernel(
    const float* __restrict__ W, __half* __restrict__ Thi, int K, int N)
{
    __shared__ float tile[32][33];
    int n0 = blockIdx.x * 32, k0 = blockIdx.y * 32;
    int tx = threadIdx.x & 31, ty = threadIdx.x >> 5;
#pragma unroll
    for (int j = 0; j < 4; j++)
        tile[ty + 8 * j][tx] = W[(size_t)(k0 + ty + 8 * j) * N + n0 + tx];
    __syncthreads();
#pragma unroll
    for (int j = 0; j < 4; j++) {
        int n = ty + 8 * j;
        Thi[(size_t)(n0 + n) * K + k0 + tx] = __float2half(tile[tx][n]);
    }
}

// ---------------- GEMM common geometry ----------------
#define PITCH   80
#define T_A     10240                  // 128 rows * 80B

// ---------------- bf16 3-MMA GEMM: C = A(hi/lo) * B(hi/lo)^T ----------------
#define T_STAGE (4 * T_A)
#define G_SMEM  (2 * T_STAGE)          // 81920

__device__ __forceinline__ void g_load_pair(
    uint32_t sbase, const __nv_bfloat16* __restrict__ hi,
    const __nv_bfloat16* __restrict__ lo, int rbase, int kc, int K, int tid)
{
#pragma unroll
    for (int i = 0; i < 2; i++) {
        int s = tid + 256 * i;
        int row = s >> 2, part = s & 3;
        size_t go = (size_t)(rbase + row) * K + (size_t)kc * 32 + part * 8;
        uint32_t so = (uint32_t)(row * PITCH + part * 16);
        CP_ASYNC16(sbase + so, hi + go);
        CP_ASYNC16(sbase + T_A + so, lo + go);
    }
}

__global__ void __launch_bounds__(256) tcgemm_kernel(
    const __nv_bfloat16* __restrict__ Ahi, const __nv_bfloat16* __restrict__ Alo,
    const __nv_bfloat16* __restrict__ Bhi, const __nv_bfloat16* __restrict__ Blo,
    float* __restrict__ C, int N, int K)
{
    extern __shared__ char smc[];
    const uint32_t sb0 = smem_u32(smc);
    const int tid  = threadIdx.x;
    const int lane = tid & 31;
    const int wid  = tid >> 5;
    const int wm   = wid & 1;
    const int wn   = wid >> 1;
    const int row0 = blockIdx.y * 128;
    const int col0 = blockIdx.x * 128;

    float acc[4][4][4];
#pragma unroll
    for (int m = 0; m < 4; m++)
#pragma unroll
        for (int n = 0; n < 4; n++)
#pragma unroll
            for (int e = 0; e < 4; e++) acc[m][n][e] = 0.f;

    const uint32_t a_row = (uint32_t)(wm * 64 + (lane & 15));
    const uint32_t a_kb  = (uint32_t)((lane >> 4) * 16);
    const int bmat = lane >> 3, bwin = lane & 7;
    const uint32_t b_n  = (uint32_t)(wn * 32 + bwin + (bmat >> 1) * 8);
    const uint32_t b_kb = (uint32_t)((bmat & 1) * 16);

    const int nk = K >> 5;

    g_load_pair(sb0,           Ahi, Alo, row0, 0, K, tid);
    g_load_pair(sb0 + 2 * T_A, Bhi, Blo, col0, 0, K, tid);
    CP_COMMIT();

    for (int kc = 0; kc < nk; kc++) {
        uint32_t sb = sb0 + (uint32_t)(kc & 1) * T_STAGE;
        if (kc + 1 < nk) {
            uint32_t sb2 = sb0 + (uint32_t)((kc + 1) & 1) * T_STAGE;
            g_load_pair(sb2,           Ahi, Alo, row0, kc + 1, K, tid);
            g_load_pair(sb2 + 2 * T_A, Bhi, Blo, col0, kc + 1, K, tid);
            CP_COMMIT();
            CP_WAIT(1);
        } else {
            CP_WAIT(0);
        }
        __syncthreads();

        const uint32_t aB = sb + a_row * PITCH + a_kb;
        const uint32_t bB = sb + 2 * T_A + b_n * PITCH + b_kb;

#pragma unroll
        for (int ks = 0; ks < 2; ks++) {
            uint32_t ah[4][4], al[4][4], bh[2][4], bl[2][4];
#pragma unroll
            for (int m = 0; m < 4; m++) {
                ldsm4(ah[m], aB + (uint32_t)(m * 16 * PITCH) + ks * 32);
                ldsm4(al[m], aB + T_A + (uint32_t)(m * 16 * PITCH) + ks * 32);
            }
#pragma unroll
            for (int p = 0; p < 2; p++) {
                ldsm4(bh[p], bB + (uint32_t)(p * 16 * PITCH) + ks * 32);
                ldsm4(bl[p], bB + T_A + (uint32_t)(p * 16 * PITCH) + ks * 32);
            }
#pragma unroll
            for (int m = 0; m < 4; m++)
#pragma unroll
                for (int p = 0; p < 2; p++)
#pragma unroll
                    for (int h = 0; h < 2; h++) {
                        float* c = acc[m][p * 2 + h];
                        uint32_t bhh[2] = {bh[p][h * 2], bh[p][h * 2 + 1]};
                        uint32_t bll[2] = {bl[p][h * 2], bl[p][h * 2 + 1]};
                        mma_bf16(c, ah[m], bhh);
                        mma_bf16(c, ah[m], bll);
                        mma_bf16(c, al[m], bhh);
                    }
        }
        __syncthreads();
    }

    const int g = lane >> 2, t = lane & 3;
#pragma unroll
    for (int m = 0; m < 4; m++) {
        int r0 = row0 + wm * 64 + m * 16 + g;
#pragma unroll
        for (int n = 0; n < 4; n++) {
            int c = col0 + wn * 32 + n * 8 + 2 * t;
            *(float2*)&C[(size_t)r0 * N + c] = make_float2(acc[m][n][0], acc[m][n][1]);
            *(float2*)&C[(size_t)(r0 + 8) * N + c] = make_float2(acc[m][n][2], acc[m][n][3]);
        }
    }
}

// ---------------- fp16 2-MMA GEMM: C = (Ahi+Alo) * Bhi^T ----------------
#define T2_STAGE (3 * T_A)             // Ah, Al, Bh
#define G2_SMEM  (2 * T2_STAGE)        // 61440

__global__ void __launch_bounds__(256) tcgemm2_kernel(
    const __half* __restrict__ Ahi, const __half* __restrict__ Alo,
    const __half* __restrict__ Bhi,
    float* __restrict__ C, int N, int K)
{
    extern __shared__ char smc[];
    const uint32_t sb0 = smem_u32(smc);
    const int tid  = threadIdx.x;
    const int lane = tid & 31;
    const int wid  = tid >> 5;
    const int wm   = wid & 1;
    const int wn   = wid >> 1;
    const int row0 = blockIdx.y * 128;
    const int col0 = blockIdx.x * 128;

    float acc[4][4][4];
#pragma unroll
    for (int m = 0; m < 4; m++)
#pragma unroll
        for (int n = 0; n < 4; n++)
#pragma unroll
            for (int e = 0; e < 4; e++) acc[m][n][e] = 0.f;

    const uint32_t a_row = (uint32_t)(wm * 64 + (lane & 15));
    const uint32_t a_kb  = (uint32_t)((lane >> 4) * 16);
    const int bmat = lane >> 3, bwin = lane & 7;
    const uint32_t b_n  = (uint32_t)(wn * 32 + bwin + (bmat >> 1) * 8);
    const uint32_t b_kb = (uint32_t)((bmat & 1) * 16);

    const int nk = K >> 5;

    auto load_stage = [&](uint32_t sb, int kc) {
#pragma unroll
        for (int i = 0; i < 2; i++) {
            int s = tid + 256 * i;
            int row = s >> 2, part = s & 3;
            size_t goA = (size_t)(row0 + row) * K + (size_t)kc * 32 + part * 8;
            size_t goB = (size_t)(col0 + row) * K + (size_t)kc * 32 + part * 8;
            uint32_t so = (uint32_t)(row * PITCH + part * 16);
            CP_ASYNC16(sb + so,           Ahi + goA);
            CP_ASYNC16(sb + T_A + so,     Alo + goA);
            CP_ASYNC16(sb + 2 * T_A + so, Bhi + goB);
        }
    };

    load_stage(sb0, 0);
    CP_COMMIT();

    for (int kc = 0; kc < nk; kc++) {
        uint32_t sb = sb0 + (uint32_t)(kc & 1) * T2_STAGE;
        if (kc + 1 < nk) {
            load_stage(sb0 + (uint32_t)((kc + 1) & 1) * T2_STAGE, kc + 1);
            CP_COMMIT();
            CP_WAIT(1);
        } else {
            CP_WAIT(0);
        }
        __syncthreads();

        const uint32_t aB = sb + a_row * PITCH + a_kb;
        const uint32_t bB = sb + 2 * T_A + b_n * PITCH + b_kb;

#pragma unroll
        for (int ks = 0; ks < 2; ks++) {
            uint32_t ah[4][4], al[4][4], bh[2][4];
#pragma unroll
            for (int m = 0; m < 4; m++) {
                ldsm4(ah[m], aB + (uint32_t)(m * 16 * PITCH) + ks * 32);
                ldsm4(al[m], aB + T_A + (uint32_t)(m * 16 * PITCH) + ks * 32);
            }
#pragma unroll
            for (int p = 0; p < 2; p++)
                ldsm4(bh[p], bB + (uint32_t)(p * 16 * PITCH) + ks * 32);
#pragma unroll
            for (int m = 0; m < 4; m++)
#pragma unroll
                for (int p = 0; p < 2; p++)
#pragma unroll
                    for (int h = 0; h < 2; h++) {
                        float* c = acc[m][p * 2 + h];
                        uint32_t bhh[2] = {bh[p][h * 2], bh[p][h * 2 + 1]};
                        mma_f16(c, ah[m], bhh);
                        mma_f16(c, al[m], bhh);
                    }
        }
        __syncthreads();
    }

    const int g = lane >> 2, t = lane & 3;
#pragma unroll
    for (int m = 0; m < 4; m++) {
        int r0 = row0 + wm * 64 + m * 16 + g;
#pragma unroll
        for (int n = 0; n < 4; n++) {
            int c = col0 + wn * 32 + n * 8 + 2 * t;
            *(float2*)&C[(size_t)r0 * N + c] = make_float2(acc[m][n][0], acc[m][n][1]);
            *(float2*)&C[(size_t)(r0 + 8) * N + c] = make_float2(acc[m][n][2], acc[m][n][3]);
        }
    }
}

// ---------------- RoPE on q -> head-major hi/lo bf16 ----------------
__global__ void __launch_bounds__(256) rope_q_kernel(
    const float* __restrict__ cosb, const float* __restrict__ sinb)
{
    int idx = blockIdx.x * 256 + threadIdx.x;
    if (idx >= NH * Tn * 64) return;
    int d = idx & 63;
    int t = (idx >> 6) & (Tn - 1);
    int h = idx >> 17;
    float u1 = g_tq[t * HDq + h * Dh + d];
    float u2 = g_tq[t * HDq + h * Dh + d + 64];
    float c1 = cosb[t * Dh + d],      s1 = sinb[t * Dh + d];
    float c2 = cosb[t * Dh + d + 64], s2 = sinb[t * Dh + d + 64];
    float y1 = u1 * c1 - u2 * s1;
    float y2 = u2 * c2 + u1 * s2;
    size_t o = ((size_t)h * Tn + t) * Dh + d;
    __nv_bfloat16 h1 = __float2bfloat16(y1), h2 = __float2bfloat16(y2);
    g_qhi[o]      = h1;
    g_qlo[o]      = __float2bfloat16(y1 - __bfloat162float(h1));
    g_qhi[o + 64] = h2;
    g_qlo[o + 64] = __float2bfloat16(y2 - __bfloat162float(h2));
}

// ---------------- RoPE on k + v -> planes + fp32 secondary outputs ----------------
__global__ void __launch_bounds__(256) rope_kv_kernel(
    const float* __restrict__ cosb, const float* __restrict__ sinb,
    float* __restrict__ outK, float* __restrict__ outV)
{
    int idx = blockIdx.x * 256 + threadIdx.x;
    if (idx >= NKV * Tn * 64) return;
    int d  = idx & 63;
    int t  = (idx >> 6) & (Tn - 1);
    int kh = idx >> 17;
    float u1 = g_tkv[t * HD2 + kh * Dh + d];
    float u2 = g_tkv[t * HD2 + kh * Dh + d + 64];
    float c1 = cosb[t * Dh + d],      s1 = sinb[t * Dh + d];
    float c2 = cosb[t * Dh + d + 64], s2 = sinb[t * Dh + d + 64];
    float y1 = u1 * c1 - u2 * s1;
    float y2 = u2 * c2 + u1 * s2;
    size_t o = ((size_t)kh * Tn + t) * Dh + d;
    outK[o]      = y1;
    outK[o + 64] = y2;
    __nv_bfloat16 h1 = __float2bfloat16(y1), h2 = __float2bfloat16(y2);
    g_khi[o]      = h1;
    g_klo[o]      = __float2bfloat16(y1 - __bfloat162float(h1));
    g_khi[o + 64] = h2;
    g_klo[o + 64] = __float2bfloat16(y2 - __bfloat162float(h2));
    float v1 = g_tkv[t * HD2 + HDkv + kh * Dh + d];
    float v2 = g_tkv[t * HD2 + HDkv + kh * Dh + d + 64];
    outV[o]      = v1;
    outV[o + 64] = v2;
    g_vh[o]      = __float2half(v1);
    g_vh[o + 64] = __float2half(v2);
}

// ---------------- flash attention (QK: bf16 3-MMA, PV: fp16 2-MMA) ----------------
// BM=128, BN=64. 8 warps, each owns 16 rows full width. grid (16, NH), 256 thr.
#define FP272   272
#define QTILE   (128 * FP272)          // 34816
#define KTILE   (64 * FP272)           // 17408
#define FSTAGE  (3 * KTILE)            // Kh, Kl, Vh = 52224
#define F_SMEM  (2 * QTILE + 2 * FSTAGE)  // 174080

__device__ __forceinline__ void f_load_kv(
    uint32_t st, const __nv_bfloat16* __restrict__ kh,
    const __nv_bfloat16* __restrict__ kl, const __half* __restrict__ vh, int tid)
{
#pragma unroll
    for (int i = 0; i < 4; i++) {
        int s = tid + 256 * i;             // 1024 chunks of 16B per tile
        int r = s >> 4, c = s & 15;
        uint32_t so = (uint32_t)(r * FP272 + c * 16);
        size_t go = (size_t)r * Dh + c * 8;
        CP_ASYNC16(st + so,             kh + go);
        CP_ASYNC16(st + KTILE + so,     kl + go);
        CP_ASYNC16(st + 2 * KTILE + so, vh + go);
    }
}

__global__ void __launch_bounds__(256) flash_mma_kernel(
    __half* __restrict__ ybhi, __half* __restrict__ yblo)
{
    extern __shared__ char smc[];
    const uint32_t sb = smem_u32(smc);
    const int tid = threadIdx.x, lane = tid & 31, w = tid >> 5;
    const int h  = blockIdx.y;
    const int qi = (int)gridDim.x - 1 - (int)blockIdx.x;   // big tiles first
    const int q0 = qi * 128;
    const int kvh = h >> 2;
    const int nb = 2 * qi + 2;

    const uint32_t sQh = sb, sQl = sb + QTILE;
    const uint32_t sKV = sb + 2 * QTILE;

    const uint32_t aQoff = (uint32_t)((16 * w + (lane & 15)) * FP272 + (lane >> 4) * 16);
    const int bmat = lane >> 3, bwin = lane & 7;
    const uint32_t bKoff = (uint32_t)((bwin + ((bmat >> 1) << 3)) * FP272 + ((bmat & 1) << 4));
    const uint32_t bVoff = (uint32_t)((lane & 15) * FP272 + ((lane >> 4) << 4));

    {
        const __nv_bfloat16* gqh = g_qhi + ((size_t)h * Tn + q0) * Dh;
        const __nv_bfloat16* gql = g_qlo + ((size_t)h * Tn + q0) * Dh;
#pragma unroll
        for (int i = 0; i < 8; i++) {
            int s = tid + 256 * i;
            int r = s >> 4, c = s & 15;
            uint32_t so = (uint32_t)(r * FP272 + c * 16);
            size_t go = (size_t)r * Dh + c * 8;
            CP_ASYNC16(sQh + so, gqh + go);
            CP_ASYNC16(sQl + so, gql + go);
        }
        f_load_kv(sKV, g_khi + (size_t)kvh * Tn * Dh, g_klo + (size_t)kvh * Tn * Dh,
                  g_vh + (size_t)kvh * Tn * Dh, tid);
        CP_COMMIT();
    }

    float o[16][4];
#pragma unroll
    for (int dt = 0; dt < 16; dt++)
#pragma unroll
        for (int e = 0; e < 4; e++) o[dt][e] = 0.f;
    float m0 = -1e30f, m1 = -1e30f, l0 = 0.f, l1 = 0.f;

    const int row_lo = q0 + 16 * w + (lane >> 2);
    const int row_hi = row_lo + 8;

    for (int j = 0; j < nb; j++) {
        if (j + 1 < nb) {
            size_t kb = (size_t)(j + 1) * 64;
            uint32_t st2 = sKV + (uint32_t)((j + 1) & 1) * FSTAGE;
            f_load_kv(st2,
                      g_khi + ((size_t)kvh * Tn + kb) * Dh,
                      g_klo + ((size_t)kvh * Tn + kb) * Dh,
                      g_vh  + ((size_t)kvh * Tn + kb) * Dh, tid);
            CP_COMMIT();
            CP_WAIT(1);
        } else {
            CP_WAIT(0);
        }
        __syncthreads();

        const uint32_t stg = sKV + (uint32_t)(j & 1) * FSTAGE;
        const int kb0 = j * 64;
        const bool active = (q0 + 16 * w + 15) >= kb0;

        if (active) {
            float sc[8][4];
#pragma unroll
            for (int nt = 0; nt < 8; nt++)
#pragma unroll
                for (int e = 0; e < 4; e++) sc[nt][e] = 0.f;

#pragma unroll
            for (int ks = 0; ks < 8; ks++) {
                uint32_t qh_f[4], ql_f[4];
                ldsm4(qh_f, sQh + aQoff + ks * 32);
                ldsm4(ql_f, sQl + aQoff + ks * 32);
#pragma unroll
                for (int p = 0; p < 4; p++) {
                    uint32_t khf[4], klf[4];
                    uint32_t ka = stg + bKoff + (uint32_t)(p * 16 * FP272) + ks * 32;
                    ldsm4(khf, ka);
                    ldsm4(klf, ka + KTILE);
#pragma unroll
                    for (int hh = 0; hh < 2; hh++) {
                        float* c = sc[p * 2 + hh];
                        uint32_t bh2[2] = {khf[hh * 2], khf[hh * 2 + 1]};
                        uint32_t bl2[2] = {klf[hh * 2], klf[hh * 2 + 1]};
                        mma_bf16(c, qh_f, bh2);
                        mma_bf16(c, qh_f, bl2);
                        mma_bf16(c, ql_f, bh2);
                    }
                }
            }

            if (kb0 + 63 > row_lo) {
#pragma unroll
                for (int nt = 0; nt < 8; nt++) {
                    int col = kb0 + nt * 8 + 2 * (lane & 3);
                    if (col > row_lo)     sc[nt][0] = -1e30f;
                    if (col + 1 > row_lo) sc[nt][1] = -1e30f;
                    if (col > row_hi)     sc[nt][2] = -1e30f;
                    if (col + 1 > row_hi) sc[nt][3] = -1e30f;
                }
            }

            float ml0 = -1e30f, ml1 = -1e30f;
#pragma unroll
            for (int nt = 0; nt < 8; nt++) {
                ml0 = fmaxf(ml0, fmaxf(sc[nt][0], sc[nt][1]));
                ml1 = fmaxf(ml1, fmaxf(sc[nt][2], sc[nt][3]));
            }
            ml0 = fmaxf(ml0, __shfl_xor_sync(0xffffffffu, ml0, 1));
            ml0 = fmaxf(ml0, __shfl_xor_sync(0xffffffffu, ml0, 2));
            ml1 = fmaxf(ml1, __shfl_xor_sync(0xffffffffu, ml1, 1));
            ml1 = fmaxf(ml1, __shfl_xor_sync(0xffffffffu, ml1, 2));
            float mn0 = fmaxf(m0, ml0), mn1 = fmaxf(m1, ml1);
            float es0 = __expf(m0 - mn0), es1 = __expf(m1 - mn1);
            float ls0 = 0.f, ls1 = 0.f;
#pragma unroll
            for (int nt = 0; nt < 8; nt++) {
                sc[nt][0] = __expf(sc[nt][0] - mn0);
                sc[nt][1] = __expf(sc[nt][1] - mn0);
                sc[nt][2] = __expf(sc[nt][2] - mn1);
                sc[nt][3] = __expf(sc[nt][3] - mn1);
                ls0 += sc[nt][0] + sc[nt][1];
                ls1 += sc[nt][2] + sc[nt][3];
            }
            ls0 += __shfl_xor_sync(0xffffffffu, ls0, 1);
            ls0 += __shfl_xor_sync(0xffffffffu, ls0, 2);
            ls1 += __shfl_xor_sync(0xffffffffu, ls1, 1);
            ls1 += __shfl_xor_sync(0xffffffffu, ls1, 2);
            l0 = l0 * es0 + ls0;  m0 = mn0;
            l1 = l1 * es1 + ls1;  m1 = mn1;
#pragma unroll
            for (int dt = 0; dt < 16; dt++) {
                o[dt][0] *= es0;  o[dt][1] *= es0;
                o[dt][2] *= es1;  o[dt][3] *= es1;
            }

            // ---- O += P * V : fp16 2-MMA (P hi+lo, V hi only) ----
#pragma unroll
            for (int j2 = 0; j2 < 4; j2++) {
                uint32_t ph[4], pl[4];
                split2h(sc[2 * j2][0],     sc[2 * j2][1],     ph[0], pl[0]);
                split2h(sc[2 * j2][2],     sc[2 * j2][3],     ph[1], pl[1]);
                split2h(sc[2 * j2 + 1][0], sc[2 * j2 + 1][1], ph[2], pl[2]);
                split2h(sc[2 * j2 + 1][2], sc[2 * j2 + 1][3], ph[3], pl[3]);
#pragma unroll
                for (int dt2 = 0; dt2 < 8; dt2++) {
                    uint32_t vhf[4];
                    uint32_t va = stg + 2 * KTILE + bVoff +
                                  (uint32_t)(j2 * 16 * FP272) + (uint32_t)(dt2 * 32);
                    ldsm4t(vhf, va);
#pragma unroll
                    for (int hf = 0; hf < 2; hf++) {
                        float* c = o[dt2 * 2 + hf];
                        uint32_t bh2[2] = {vhf[hf * 2], vhf[hf * 2 + 1]};
                        mma_f16(c, ph, bh2);
                        mma_f16(c, pl, bh2);
                    }
                }
            }
        }
        __syncthreads();
    }

    // ---- epilogue: y hi/lo fp16 for the Wo GEMM ----
    float inv0 = 1.f / l0, inv1 = 1.f / l1;
#pragma unroll
    for (int dt = 0; dt < 16; dt++) {
        int d = dt * 8 + 2 * (lane & 3);
        size_t o0 = (size_t)row_lo * Cdim + h * Dh + d;
        size_t o1 = (size_t)row_hi * Cdim + h * Dh + d;
        uint32_t hi0, lo0, hi1, lo1;
        split2h(o[dt][0] * inv0, o[dt][1] * inv0, hi0, lo0);
        split2h(o[dt][2] * inv1, o[dt][3] * inv1, hi1, lo1);
        *reinterpret_cast<uint32_t*>(ybhi + o0) = hi0;
        *reinterpret_cast<uint32_t*>(yblo + o0) = lo0;
        *reinterpret_cast<uint32_t*>(ybhi + o1) = hi1;
        *reinterpret_cast<uint32_t*>(yblo + o1) = lo1;
    }
}

// ---------------- launch ----------------
extern "C" void kernel_launch(void* const* d_in, const int* in_sizes, int n_in,
                              void* d_out, int out_size)
{
    const float* x    = (const float*)d_in[0];
    const float* Wq   = (const float*)d_in[1];
    const float* Wk   = (const float*)d_in[2];
    const float* Wv   = (const float*)d_in[3];
    const float* Wo   = (const float*)d_in[4];
    const float* cosb = (const float*)d_in[5];
    const float* sinb = (const float*)d_in[6];
    // d_in[7] = mask (reproduced exactly by causal structure; unused)

    float* out  = (float*)d_out;
    float* outY = out;
    float* outK = out + (size_t)Tn * Cdim;
    float* outV = outK + (size_t)NKV * Tn * Dh;

    float *tq, *tkv;
    cudaGetSymbolAddress((void**)&tq, g_tq);
    cudaGetSymbolAddress((void**)&tkv, g_tkv);
    __nv_bfloat16 *xhi, *xlo, *wqhi, *wqlo, *wkvhi, *wkvlo;
    __half *ybhi, *yblo, *wohi;
    cudaGetSymbolAddress((void**)&xhi, g_xhi);
    cudaGetSymbolAddress((void**)&xlo, g_xlo);
    cudaGetSymbolAddress((void**)&wqhi, g_wqhi);
    cudaGetSymbolAddress((void**)&wqlo, g_wqlo);
    cudaGetSymbolAddress((void**)&wkvhi, g_wkvhi);
    cudaGetSymbolAddress((void**)&wkvlo, g_wkvlo);
    cudaGetSymbolAddress((void**)&ybhi, g_ybhi);
    cudaGetSymbolAddress((void**)&yblo, g_yblo);
    cudaGetSymbolAddress((void**)&wohi, g_wohi);

    cudaFuncSetAttribute(tcgemm_kernel, cudaFuncAttributeMaxDynamicSharedMemorySize,
                         G_SMEM);
    cudaFuncSetAttribute(tcgemm2_kernel, cudaFuncAttributeMaxDynamicSharedMemorySize,
                         G2_SMEM);
    cudaFuncSetAttribute(flash_mma_kernel, cudaFuncAttributeMaxDynamicSharedMemorySize,
                         F_SMEM);

    // 0. split/transpose prep
    split_kernel<<<(Tn * Cdim) / 256, 256>>>(x, xhi, xlo);
    tsplit_kernel<<<dim3(HDq / 32, Cdim / 32), 256>>>(Wq, wqhi, wqlo, Cdim, HDq);
    tsplit_kernel<<<dim3(HDkv / 32, Cdim / 32), 256>>>(Wk, wkvhi, wkvlo, Cdim, HDkv);
    tsplit_kernel<<<dim3(HDkv / 32, Cdim / 32), 256>>>(
        Wv, wkvhi + (size_t)HDkv * Cdim, wkvlo + (size_t)HDkv * Cdim, Cdim, HDkv);
    tsplit_h_kernel<<<dim3(Cdim / 32, Cdim / 32), 256>>>(Wo, wohi, Cdim, Cdim);

    // 1-2. projections: Q (bf16 3-MMA), merged K|V (bf16 3-MMA)
    tcgemm_kernel<<<dim3(HDq / 128, Tn / 128), 256, G_SMEM>>>(
        xhi, xlo, wqhi, wqlo, tq, HDq, Cdim);
    tcgemm_kernel<<<dim3(HD2 / 128, Tn / 128), 256, G_SMEM>>>(
        xhi, xlo, wkvhi, wkvlo, tkv, HD2, Cdim);

    // 3-4. RoPE + plane conversion (k/v fp32 copies are final outputs)
    rope_q_kernel<<<(NH * Tn * 64) / 256, 256>>>(cosb, sinb);
    rope_kv_kernel<<<(NKV * Tn * 64) / 256, 256>>>(cosb, sinb, outK, outV);

    // 5. causal flash attention (tensor cores)
    flash_mma_kernel<<<dim3(Tn / 128, NH), 256, F_SMEM>>>(ybhi, yblo);

    // 6. output projection (fp16 2-MMA)
    tcgemm2_kernel<<<dim3(Cdim / 128, Tn / 128), 256, G2_SMEM>>>(
        ybhi, yblo, wohi, outY, Cdim, Cdim);
}